// round 3
// baseline (speedup 1.0000x reference)
#include <cuda_runtime.h>
#include <math.h>

namespace {

constexpr int Bb  = 8;
constexpr int Hh  = 112;
constexpr int Ww  = 112;
constexpr int C   = 192;
constexpr int NH  = 6;
constexpr int HD  = 32;      // C / NH
constexpr int WS  = 7;
constexpr int SS  = 3;
constexpr int N   = 49;      // WS*WS
constexpr int WG  = Hh / WS; // 16
constexpr int NW  = WG * WG; // 256
constexpr int BW  = Bb * NW; // 2048
constexpr int T   = BW * N;  // 100352 tokens
constexpr int C4  = 4 * C;   // 768
constexpr float EPS    = 1e-5f;
constexpr float LOG100 = 4.605170185988091f;

// ---------------- scratch (static device globals; no allocation) -----------
__device__ float g_win [(size_t)T * C];   // gathered windows; later attn output
__device__ float g_q   [(size_t)T * C];   // q; later proj output
__device__ float g_k   [(size_t)T * C];   // k; later hidden
__device__ float g_v   [(size_t)T * C];   // v; later mlp output
__device__ float g_mlp1[(size_t)T * C4];  // fc1 output
__device__ float g_cpb [169 * NH];        // CPB MLP output table (169 x NH)
__device__ float g_scl [NH];              // per-head logit scale

// ---------------- CPB bias table MLP: (169,2)->512(relu)->NH ---------------
__global__ void cpb_kernel(const float* __restrict__ w0, const float* __restrict__ b0,
                           const float* __restrict__ w1, const float* __restrict__ ls) {
    int r   = blockIdx.x;     // 0..168
    int tid = threadIdx.x;    // 256 threads
    __shared__ float part[256][NH];

    int ri = r / 13, rj = r % 13;
    float t0 = (ri - 6) * (8.0f / 6.0f);
    float t1 = (rj - 6) * (8.0f / 6.0f);
    float v0 = copysignf(log2f(fabsf(t0) + 1.0f) * (1.0f / 3.0f), t0);
    float v1 = copysignf(log2f(fabsf(t1) + 1.0f) * (1.0f / 3.0f), t1);

    float acc[NH];
    #pragma unroll
    for (int h = 0; h < NH; ++h) acc[h] = 0.0f;
    for (int j = tid; j < 512; j += 256) {
        float hv = fmaxf(v0 * w0[j] + v1 * w0[512 + j] + b0[j], 0.0f);
        #pragma unroll
        for (int h = 0; h < NH; ++h) acc[h] += hv * w1[j * NH + h];
    }
    #pragma unroll
    for (int h = 0; h < NH; ++h) part[tid][h] = acc[h];
    __syncthreads();
    if (tid < NH) {
        float s = 0.0f;
        for (int i = 0; i < 256; ++i) s += part[i][tid];
        g_cpb[r * NH + tid] = s;
        if (r == 0) g_scl[tid] = expf(fminf(ls[tid], LOG100));
    }
}

// ---------------- cyclic shift + window partition gather -------------------
__global__ void gather_kernel(const float* __restrict__ x) {
    int t  = blockIdx.x;          // window-layout token
    int bw = t / N, n = t % N;
    int b  = bw / NW, w_ = bw % NW;
    int wy = w_ / WG, wx = w_ % WG;
    int hh = wy * WS + n / WS, ww = wx * WS + n % WS;
    int oh = (hh + SS) % Hh, ow = (ww + SS) % Ww;
    size_t src = ((size_t)(b * Hh + oh) * Ww + ow) * C;
    g_win[(size_t)t * C + threadIdx.x] = x[src + threadIdx.x];
}

// ---------------- fp32 SGEMM: C = act(A@B + bias) --------------------------
// A: MxK row-major, B: KxN row-major. M%128==0, N%64==0, K%16==0.
constexpr int BM = 128, BN = 64, BK = 16, TM = 8, TN = 8;

__device__ __forceinline__ float gelu_tanh(float v) {
    return 0.5f * v * (1.0f + tanhf(0.7978845608028654f * (v + 0.044715f * v * v * v)));
}

__global__ __launch_bounds__(128, 4)
void sgemm_kernel(const float* __restrict__ A, const float* __restrict__ B,
                  const float* __restrict__ bias, float* __restrict__ Cmat,
                  int M, int Nn, int K, int act) {
    __shared__ float As[BK][BM + 1];
    __shared__ float Bs[BK][BN];

    int tid = threadIdx.x;                 // 0..127
    int bm  = blockIdx.y * BM;
    int bn  = blockIdx.x * BN;
    int trow = (tid >> 3) * TM;            // 16 groups of 8
    int tcol = (tid & 7) * TN;

    float acc[TM][TN];
    #pragma unroll
    for (int i = 0; i < TM; ++i)
        #pragma unroll
        for (int j = 0; j < TN; ++j) acc[i][j] = 0.0f;

    for (int kt = 0; kt < K; kt += BK) {
        #pragma unroll
        for (int i = 0; i < 4; ++i) {              // A tile: 128x16
            int idx = tid + i * 128;
            int row = idx >> 2;
            int k4  = (idx & 3) * 4;
            float4 a = *reinterpret_cast<const float4*>(
                &A[(size_t)(bm + row) * K + kt + k4]);
            As[k4 + 0][row] = a.x; As[k4 + 1][row] = a.y;
            As[k4 + 2][row] = a.z; As[k4 + 3][row] = a.w;
        }
        #pragma unroll
        for (int i = 0; i < 2; ++i) {              // B tile: 16x64
            int idx = tid + i * 128;
            int row = idx >> 4;
            int c4  = (idx & 15) * 4;
            *reinterpret_cast<float4*>(&Bs[row][c4]) =
                *reinterpret_cast<const float4*>(&B[(size_t)(kt + row) * Nn + bn + c4]);
        }
        __syncthreads();
        #pragma unroll
        for (int kk = 0; kk < BK; ++kk) {
            float af[TM], bf[TN];
            #pragma unroll
            for (int i = 0; i < TM; ++i) af[i] = As[kk][trow + i];
            #pragma unroll
            for (int j = 0; j < TN; ++j) bf[j] = Bs[kk][tcol + j];
            #pragma unroll
            for (int i = 0; i < TM; ++i)
                #pragma unroll
                for (int j = 0; j < TN; ++j) acc[i][j] += af[i] * bf[j];
        }
        __syncthreads();
    }

    #pragma unroll
    for (int i = 0; i < TM; ++i) {
        size_t rbase = (size_t)(bm + trow + i) * Nn + bn + tcol;
        #pragma unroll
        for (int j = 0; j < TN; ++j) {
            float v = acc[i][j];
            if (bias) v += bias[bn + tcol + j];
            if (act == 1) v = gelu_tanh(v);
            Cmat[rbase + j] = v;
        }
    }
}

// ---------------- fused per-(window,head) attention -------------------------
__global__ __launch_bounds__(256)
void attn_kernel() {
    int blk = blockIdx.x;          // 0..BW*NH-1
    int bw  = blk / NH, h = blk % NH;
    int tid = threadIdx.x;

    __shared__ float qs[N * HD], ks[N * HD], vs[N * HD];
    __shared__ float lg[N * N];
    __shared__ int   rgn[N];
    __shared__ float scale_s;

    if (tid == 0) scale_s = g_scl[h];

    for (int e = tid; e < N * HD; e += blockDim.x) {
        int n = e / HD, d = e % HD;
        size_t base = (size_t)(bw * N + n) * C + h * HD + d;
        qs[e] = g_q[base]; ks[e] = g_k[base]; vs[e] = g_v[base];
    }
    if (tid < N) {
        int w_ = bw % NW, wy = w_ / WG, wx = w_ % WG;
        int gh = wy * WS + tid / WS, gw = wx * WS + tid % WS;
        int rh = gh < Hh - WS ? 0 : (gh < Hh - SS ? 1 : 2);
        int rw = gw < Ww - WS ? 0 : (gw < Ww - SS ? 1 : 2);
        rgn[tid] = rh * 3 + rw;
    }
    __syncthreads();

    // cosine-normalize rows (q also absorbs the logit scale)
    if (tid < 2 * N) {
        float* arr = (tid < N) ? qs : ks;
        int r = (tid < N) ? tid : tid - N;
        float ssum = 0.0f;
        #pragma unroll
        for (int d = 0; d < HD; ++d) { float u = arr[r * HD + d]; ssum += u * u; }
        float inv = 1.0f / fmaxf(sqrtf(ssum), 1e-12f);
        if (tid < N) inv *= scale_s;
        #pragma unroll
        for (int d = 0; d < HD; ++d) arr[r * HD + d] *= inv;
    }
    __syncthreads();

    // logits + CPB bias + shift mask
    for (int l = tid; l < N * N; l += blockDim.x) {
        int i = l / N, j = l % N;
        float dot = 0.0f;
        #pragma unroll
        for (int d = 0; d < HD; ++d) dot += qs[i * HD + d] * ks[j * HD + d];
        int idx = ((i / WS - j / WS) + WS - 1) * (2 * WS - 1)
                + ((i % WS - j % WS) + WS - 1);
        float b = g_cpb[idx * NH + h];
        float sig = 16.0f / (1.0f + expf(-b));
        float m = (rgn[i] != rgn[j]) ? -100.0f : 0.0f;
        lg[l] = dot + sig + m;
    }
    __syncthreads();

    // row softmax
    if (tid < N) {
        float mx = -1e30f;
        for (int j = 0; j < N; ++j) mx = fmaxf(mx, lg[tid * N + j]);
        float s = 0.0f;
        for (int j = 0; j < N; ++j) {
            float e = expf(lg[tid * N + j] - mx);
            lg[tid * N + j] = e; s += e;
        }
        float inv = 1.0f / s;
        for (int j = 0; j < N; ++j) lg[tid * N + j] *= inv;
    }
    __syncthreads();

    // out = attn @ v  -> write into g_win (window layout, head-interleaved)
    for (int e = tid; e < N * HD; e += blockDim.x) {
        int i = e / HD, d = e % HD;
        float a = 0.0f;
        #pragma unroll
        for (int j = 0; j < N; ++j) a += lg[i * N + j] * vs[j * HD + d];
        g_win[(size_t)(bw * N + i) * C + h * HD + d] = a;
    }
}

// ---------------- block-wide sum over 192 threads ---------------------------
__device__ __forceinline__ float block_sum192(float v, float* red) {
    #pragma unroll
    for (int o = 16; o > 0; o >>= 1) v += __shfl_down_sync(0xffffffffu, v, o);
    int wid = threadIdx.x >> 5;
    if ((threadIdx.x & 31) == 0) red[wid] = v;
    __syncthreads();
    float s = red[0] + red[1] + red[2] + red[3] + red[4] + red[5];
    __syncthreads();
    return s;
}

// hidden[dst] = x[dst] + LN1(proj[t]), with window-reverse + un-shift scatter
__global__ __launch_bounds__(192)
void postattn_kernel(const float* __restrict__ x,
                     const float* __restrict__ g1, const float* __restrict__ b1) {
    __shared__ float red[6];
    int t = blockIdx.x, c = threadIdx.x;
    int bw = t / N, n = t % N;
    int b  = bw / NW, w_ = bw % NW;
    int wy = w_ / WG, wx = w_ % WG;
    int hh = wy * WS + n / WS, ww = wx * WS + n % WS;
    int oh = (hh + SS) % Hh, ow = (ww + SS) % Ww;
    size_t dst = ((size_t)(b * Hh + oh) * Ww + ow) * C;

    float v = g_q[(size_t)t * C + c];          // proj output row
    float mean = block_sum192(v, red) * (1.0f / C);
    float dv = v - mean;
    float var = block_sum192(dv * dv, red) * (1.0f / C);
    float ln = dv * rsqrtf(var + EPS) * g1[c] + b1[c];
    g_k[dst + c] = x[dst + c] + ln;            // hidden (natural layout)
}

// out[t] = hidden[t] + LN2(mlp[t])
__global__ __launch_bounds__(192)
void final_kernel(const float* __restrict__ g2, const float* __restrict__ b2,
                  float* __restrict__ out) {
    __shared__ float red[6];
    int t = blockIdx.x, c = threadIdx.x;
    float v = g_v[(size_t)t * C + c];          // mlp output row
    float mean = block_sum192(v, red) * (1.0f / C);
    float dv = v - mean;
    float var = block_sum192(dv * dv, red) * (1.0f / C);
    float ln = dv * rsqrtf(var + EPS) * g2[c] + b2[c];
    out[(size_t)t * C + c] = g_k[(size_t)t * C + c] + ln;
}

} // namespace

// ============================================================================
extern "C" void kernel_launch(void* const* d_in, const int* in_sizes, int n_in,
                              void* d_out, int out_size) {
    const float* x      = (const float*)d_in[0];
    const float* ln1_g  = (const float*)d_in[1];
    const float* ln1_b  = (const float*)d_in[2];
    const float* ln2_g  = (const float*)d_in[3];
    const float* ln2_b  = (const float*)d_in[4];
    const float* q_w    = (const float*)d_in[5];
    const float* q_b    = (const float*)d_in[6];
    const float* k_w    = (const float*)d_in[7];
    const float* v_w    = (const float*)d_in[8];
    const float* v_b    = (const float*)d_in[9];
    const float* p_w    = (const float*)d_in[10];
    const float* p_b    = (const float*)d_in[11];
    const float* lscale = (const float*)d_in[12];
    const float* cpb_w0 = (const float*)d_in[13];
    const float* cpb_b0 = (const float*)d_in[14];
    const float* cpb_w1 = (const float*)d_in[15];
    const float* fc1_w  = (const float*)d_in[16];
    const float* fc1_b  = (const float*)d_in[17];
    const float* fc2_w  = (const float*)d_in[18];
    const float* fc2_b  = (const float*)d_in[19];
    float* out = (float*)d_out;

    float *p_win, *p_q, *p_k, *p_v, *p_m1;
    cudaGetSymbolAddress((void**)&p_win, g_win);
    cudaGetSymbolAddress((void**)&p_q,   g_q);
    cudaGetSymbolAddress((void**)&p_k,   g_k);
    cudaGetSymbolAddress((void**)&p_v,   g_v);
    cudaGetSymbolAddress((void**)&p_m1,  g_mlp1);

    // 1) CPB bias table + head scales
    cpb_kernel<<<169, 256>>>(cpb_w0, cpb_b0, cpb_w1, lscale);

    // 2) cyclic shift + window partition
    gather_kernel<<<T, C>>>(x);

    // 3-5) QKV GEMMs (win @ W [+ b])
    dim3 gC(C / BN, T / BM);
    sgemm_kernel<<<gC, 128>>>(p_win, q_w, q_b,     p_q, T, C, C, 0);
    sgemm_kernel<<<gC, 128>>>(p_win, k_w, nullptr, p_k, T, C, C, 0);
    sgemm_kernel<<<gC, 128>>>(p_win, v_w, v_b,     p_v, T, C, C, 0);

    // 6) fused attention (writes attn output into g_win)
    attn_kernel<<<BW * NH, 256>>>();

    // 7) output projection
    sgemm_kernel<<<gC, 128>>>(p_win, p_w, p_b, p_q, T, C, C, 0);

    // 8) window reverse + un-shift + LN1 + residual -> hidden (g_k)
    postattn_kernel<<<T, C>>>(x, ln1_g, ln1_b);

    // 9) fc1 + GELU
    dim3 gF1(C4 / BN, T / BM);
    sgemm_kernel<<<gF1, 128>>>(p_k, fc1_w, fc1_b, p_m1, T, C4, C, 1);

    // 10) fc2
    sgemm_kernel<<<gC, 128>>>(p_m1, fc2_w, fc2_b, p_v, T, C, C4, 0);

    // 11) hidden + LN2(mlp) -> out
    final_kernel<<<T, C>>>(ln2_g, ln2_b, out);
}

// round 4
// speedup vs baseline: 1.0014x; 1.0014x over previous
#include <cuda_runtime.h>
#include <math.h>

namespace {

constexpr int Bb  = 8;
constexpr int Hh  = 112;
constexpr int Ww  = 112;
constexpr int C   = 192;
constexpr int NH  = 6;
constexpr int HD  = 32;      // C / NH
constexpr int WS  = 7;
constexpr int SS  = 3;
constexpr int N   = 49;      // WS*WS
constexpr int WG  = Hh / WS; // 16
constexpr int NW  = WG * WG; // 256
constexpr int BW  = Bb * NW; // 2048
constexpr int T   = BW * N;  // 100352 tokens
constexpr int C4  = 4 * C;   // 768
constexpr float EPS    = 1e-5f;
constexpr float LOG100 = 4.605170185988091f;

// ---------------- scratch (static device globals; no allocation) -----------
__device__ float g_win [(size_t)T * C];   // gathered windows; later attn output
__device__ float g_q   [(size_t)T * C];   // q; later proj output
__device__ float g_k   [(size_t)T * C];   // k; later hidden
__device__ float g_v   [(size_t)T * C];   // v; later mlp output
__device__ float g_mlp1[(size_t)T * C4];  // fc1 output
__device__ float g_cpb [169 * NH];        // CPB MLP output table (169 x NH)
__device__ float g_scl [NH];              // per-head logit scale

// ---------------- CPB bias table MLP: (169,2)->512(relu)->NH ---------------
__global__ void cpb_kernel(const float* __restrict__ w0, const float* __restrict__ b0,
                           const float* __restrict__ w1, const float* __restrict__ ls) {
    int r   = blockIdx.x;     // 0..168
    int tid = threadIdx.x;    // 256 threads
    __shared__ float part[256][NH];

    int ri = r / 13, rj = r % 13;
    float t0 = (ri - 6) * (8.0f / 6.0f);
    float t1 = (rj - 6) * (8.0f / 6.0f);
    float v0 = copysignf(log2f(fabsf(t0) + 1.0f) * (1.0f / 3.0f), t0);
    float v1 = copysignf(log2f(fabsf(t1) + 1.0f) * (1.0f / 3.0f), t1);

    float acc[NH];
    #pragma unroll
    for (int h = 0; h < NH; ++h) acc[h] = 0.0f;
    for (int j = tid; j < 512; j += 256) {
        float hv = fmaxf(v0 * w0[j] + v1 * w0[512 + j] + b0[j], 0.0f);
        #pragma unroll
        for (int h = 0; h < NH; ++h) acc[h] += hv * w1[j * NH + h];
    }
    #pragma unroll
    for (int h = 0; h < NH; ++h) part[tid][h] = acc[h];
    __syncthreads();
    if (tid < NH) {
        float s = 0.0f;
        for (int i = 0; i < 256; ++i) s += part[i][tid];
        g_cpb[r * NH + tid] = s;
        if (r == 0) g_scl[tid] = expf(fminf(ls[tid], LOG100));
    }
}

// ---------------- cyclic shift + window partition gather -------------------
__global__ void gather_kernel(const float* __restrict__ x) {
    int t  = blockIdx.x;          // window-layout token
    int bw = t / N, n = t % N;
    int b  = bw / NW, w_ = bw % NW;
    int wy = w_ / WG, wx = w_ % WG;
    int hh = wy * WS + n / WS, ww = wx * WS + n % WS;
    int oh = (hh + SS) % Hh, ow = (ww + SS) % Ww;
    size_t src = ((size_t)(b * Hh + oh) * Ww + ow) * C;
    g_win[(size_t)t * C + threadIdx.x] = x[src + threadIdx.x];
}

// ---------------- fp32 SGEMM: C = act(A@B + bias) --------------------------
// A: MxK row-major, B: KxN row-major. M%128==0, N%64==0, K%16==0.
constexpr int BM = 128, BN = 64, BK = 16, TM = 8, TN = 8;

__device__ __forceinline__ float gelu_tanh(float v) {
    return 0.5f * v * (1.0f + tanhf(0.7978845608028654f * (v + 0.044715f * v * v * v)));
}

__global__ __launch_bounds__(128, 4)
void sgemm_kernel(const float* __restrict__ A, const float* __restrict__ B,
                  const float* __restrict__ bias, float* __restrict__ Cmat,
                  int M, int Nn, int K, int act) {
    __shared__ float As[BK][BM + 1];
    __shared__ float Bs[BK][BN];

    int tid = threadIdx.x;                 // 0..127
    int bm  = blockIdx.y * BM;
    int bn  = blockIdx.x * BN;
    int trow = (tid >> 3) * TM;            // 16 groups of 8
    int tcol = (tid & 7) * TN;

    float acc[TM][TN];
    #pragma unroll
    for (int i = 0; i < TM; ++i)
        #pragma unroll
        for (int j = 0; j < TN; ++j) acc[i][j] = 0.0f;

    for (int kt = 0; kt < K; kt += BK) {
        #pragma unroll
        for (int i = 0; i < 4; ++i) {              // A tile: 128x16
            int idx = tid + i * 128;
            int row = idx >> 2;
            int k4  = (idx & 3) * 4;
            float4 a = *reinterpret_cast<const float4*>(
                &A[(size_t)(bm + row) * K + kt + k4]);
            As[k4 + 0][row] = a.x; As[k4 + 1][row] = a.y;
            As[k4 + 2][row] = a.z; As[k4 + 3][row] = a.w;
        }
        #pragma unroll
        for (int i = 0; i < 2; ++i) {              // B tile: 16x64
            int idx = tid + i * 128;
            int row = idx >> 4;
            int c4  = (idx & 15) * 4;
            *reinterpret_cast<float4*>(&Bs[row][c4]) =
                *reinterpret_cast<const float4*>(&B[(size_t)(kt + row) * Nn + bn + c4]);
        }
        __syncthreads();
        #pragma unroll
        for (int kk = 0; kk < BK; ++kk) {
            float af[TM], bf[TN];
            #pragma unroll
            for (int i = 0; i < TM; ++i) af[i] = As[kk][trow + i];
            #pragma unroll
            for (int j = 0; j < TN; ++j) bf[j] = Bs[kk][tcol + j];
            #pragma unroll
            for (int i = 0; i < TM; ++i)
                #pragma unroll
                for (int j = 0; j < TN; ++j) acc[i][j] += af[i] * bf[j];
        }
        __syncthreads();
    }

    #pragma unroll
    for (int i = 0; i < TM; ++i) {
        size_t rbase = (size_t)(bm + trow + i) * Nn + bn + tcol;
        #pragma unroll
        for (int j = 0; j < TN; ++j) {
            float v = acc[i][j];
            if (bias) v += bias[bn + tcol + j];
            if (act == 1) v = gelu_tanh(v);
            Cmat[rbase + j] = v;
        }
    }
}

// ---------------- fused per-(window,head) attention -------------------------
__global__ __launch_bounds__(256)
void attn_kernel() {
    int blk = blockIdx.x;          // 0..BW*NH-1
    int bw  = blk / NH, h = blk % NH;
    int tid = threadIdx.x;

    __shared__ float qs[N * HD], ks[N * HD], vs[N * HD];
    __shared__ float lg[N * N];
    __shared__ int   rgn[N];
    __shared__ float scale_s;

    if (tid == 0) scale_s = g_scl[h];

    for (int e = tid; e < N * HD; e += blockDim.x) {
        int n = e / HD, d = e % HD;
        size_t base = (size_t)(bw * N + n) * C + h * HD + d;
        qs[e] = g_q[base]; ks[e] = g_k[base]; vs[e] = g_v[base];
    }
    if (tid < N) {
        int w_ = bw % NW, wy = w_ / WG, wx = w_ % WG;
        int gh = wy * WS + tid / WS, gw = wx * WS + tid % WS;
        int rh = gh < Hh - WS ? 0 : (gh < Hh - SS ? 1 : 2);
        int rw = gw < Ww - WS ? 0 : (gw < Ww - SS ? 1 : 2);
        rgn[tid] = rh * 3 + rw;
    }
    __syncthreads();

    // cosine-normalize rows (q also absorbs the logit scale)
    if (tid < 2 * N) {
        float* arr = (tid < N) ? qs : ks;
        int r = (tid < N) ? tid : tid - N;
        float ssum = 0.0f;
        #pragma unroll
        for (int d = 0; d < HD; ++d) { float u = arr[r * HD + d]; ssum += u * u; }
        float inv = 1.0f / fmaxf(sqrtf(ssum), 1e-12f);
        if (tid < N) inv *= scale_s;
        #pragma unroll
        for (int d = 0; d < HD; ++d) arr[r * HD + d] *= inv;
    }
    __syncthreads();

    // logits + CPB bias + shift mask
    for (int l = tid; l < N * N; l += blockDim.x) {
        int i = l / N, j = l % N;
        float dot = 0.0f;
        #pragma unroll
        for (int d = 0; d < HD; ++d) dot += qs[i * HD + d] * ks[j * HD + d];
        int idx = ((i / WS - j / WS) + WS - 1) * (2 * WS - 1)
                + ((i % WS - j % WS) + WS - 1);
        float b = g_cpb[idx * NH + h];
        float sig = 16.0f / (1.0f + expf(-b));
        float m = (rgn[i] != rgn[j]) ? -100.0f : 0.0f;
        lg[l] = dot + sig + m;
    }
    __syncthreads();

    // row softmax
    if (tid < N) {
        float mx = -1e30f;
        for (int j = 0; j < N; ++j) mx = fmaxf(mx, lg[tid * N + j]);
        float s = 0.0f;
        for (int j = 0; j < N; ++j) {
            float e = expf(lg[tid * N + j] - mx);
            lg[tid * N + j] = e; s += e;
        }
        float inv = 1.0f / s;
        for (int j = 0; j < N; ++j) lg[tid * N + j] *= inv;
    }
    __syncthreads();

    // out = attn @ v  -> write into g_win (window layout, head-interleaved)
    for (int e = tid; e < N * HD; e += blockDim.x) {
        int i = e / HD, d = e % HD;
        float a = 0.0f;
        #pragma unroll
        for (int j = 0; j < N; ++j) a += lg[i * N + j] * vs[j * HD + d];
        g_win[(size_t)(bw * N + i) * C + h * HD + d] = a;
    }
}

// ---------------- block-wide sum over 192 threads ---------------------------
__device__ __forceinline__ float block_sum192(float v, float* red) {
    #pragma unroll
    for (int o = 16; o > 0; o >>= 1) v += __shfl_down_sync(0xffffffffu, v, o);
    int wid = threadIdx.x >> 5;
    if ((threadIdx.x & 31) == 0) red[wid] = v;
    __syncthreads();
    float s = red[0] + red[1] + red[2] + red[3] + red[4] + red[5];
    __syncthreads();
    return s;
}

// hidden[dst] = x[dst] + LN1(proj[t]), with window-reverse + un-shift scatter
__global__ __launch_bounds__(192)
void postattn_kernel(const float* __restrict__ x,
                     const float* __restrict__ g1, const float* __restrict__ b1) {
    __shared__ float red[6];
    int t = blockIdx.x, c = threadIdx.x;
    int bw = t / N, n = t % N;
    int b  = bw / NW, w_ = bw % NW;
    int wy = w_ / WG, wx = w_ % WG;
    int hh = wy * WS + n / WS, ww = wx * WS + n % WS;
    int oh = (hh + SS) % Hh, ow = (ww + SS) % Ww;
    size_t dst = ((size_t)(b * Hh + oh) * Ww + ow) * C;

    float v = g_q[(size_t)t * C + c];          // proj output row
    float mean = block_sum192(v, red) * (1.0f / C);
    float dv = v - mean;
    float var = block_sum192(dv * dv, red) * (1.0f / C);
    float ln = dv * rsqrtf(var + EPS) * g1[c] + b1[c];
    g_k[dst + c] = x[dst + c] + ln;            // hidden (natural layout)
}

// out[t] = hidden[t] + LN2(mlp[t])
__global__ __launch_bounds__(192)
void final_kernel(const float* __restrict__ g2, const float* __restrict__ b2,
                  float* __restrict__ out) {
    __shared__ float red[6];
    int t = blockIdx.x, c = threadIdx.x;
    float v = g_v[(size_t)t * C + c];          // mlp output row
    float mean = block_sum192(v, red) * (1.0f / C);
    float dv = v - mean;
    float var = block_sum192(dv * dv, red) * (1.0f / C);
    float ln = dv * rsqrtf(var + EPS) * g2[c] + b2[c];
    out[(size_t)t * C + c] = g_k[(size_t)t * C + c] + ln;
}

} // namespace

// ============================================================================
extern "C" void kernel_launch(void* const* d_in, const int* in_sizes, int n_in,
                              void* d_out, int out_size) {
    const float* x      = (const float*)d_in[0];
    const float* ln1_g  = (const float*)d_in[1];
    const float* ln1_b  = (const float*)d_in[2];
    const float* ln2_g  = (const float*)d_in[3];
    const float* ln2_b  = (const float*)d_in[4];
    const float* q_w    = (const float*)d_in[5];
    const float* q_b    = (const float*)d_in[6];
    const float* k_w    = (const float*)d_in[7];
    const float* v_w    = (const float*)d_in[8];
    const float* v_b    = (const float*)d_in[9];
    const float* p_w    = (const float*)d_in[10];
    const float* p_b    = (const float*)d_in[11];
    const float* lscale = (const float*)d_in[12];
    const float* cpb_w0 = (const float*)d_in[13];
    const float* cpb_b0 = (const float*)d_in[14];
    const float* cpb_w1 = (const float*)d_in[15];
    const float* fc1_w  = (const float*)d_in[16];
    const float* fc1_b  = (const float*)d_in[17];
    const float* fc2_w  = (const float*)d_in[18];
    const float* fc2_b  = (const float*)d_in[19];
    float* out = (float*)d_out;

    float *p_win, *p_q, *p_k, *p_v, *p_m1;
    cudaGetSymbolAddress((void**)&p_win, g_win);
    cudaGetSymbolAddress((void**)&p_q,   g_q);
    cudaGetSymbolAddress((void**)&p_k,   g_k);
    cudaGetSymbolAddress((void**)&p_v,   g_v);
    cudaGetSymbolAddress((void**)&p_m1,  g_mlp1);

    // 1) CPB bias table + head scales
    cpb_kernel<<<169, 256>>>(cpb_w0, cpb_b0, cpb_w1, lscale);

    // 2) cyclic shift + window partition
    gather_kernel<<<T, C>>>(x);

    // 3-5) QKV GEMMs (win @ W [+ b])
    dim3 gC(C / BN, T / BM);
    sgemm_kernel<<<gC, 128>>>(p_win, q_w, q_b,     p_q, T, C, C, 0);
    sgemm_kernel<<<gC, 128>>>(p_win, k_w, nullptr, p_k, T, C, C, 0);
    sgemm_kernel<<<gC, 128>>>(p_win, v_w, v_b,     p_v, T, C, C, 0);

    // 6) fused attention (writes attn output into g_win)
    attn_kernel<<<BW * NH, 256>>>();

    // 7) output projection
    sgemm_kernel<<<gC, 128>>>(p_win, p_w, p_b, p_q, T, C, C, 0);

    // 8) window reverse + un-shift + LN1 + residual -> hidden (g_k)
    postattn_kernel<<<T, C>>>(x, ln1_g, ln1_b);

    // 9) fc1 + GELU
    dim3 gF1(C4 / BN, T / BM);
    sgemm_kernel<<<gF1, 128>>>(p_k, fc1_w, fc1_b, p_m1, T, C4, C, 1);

    // 10) fc2
    sgemm_kernel<<<gC, 128>>>(p_m1, fc2_w, fc2_b, p_v, T, C, C4, 0);

    // 11) hidden + LN2(mlp) -> out
    final_kernel<<<T, C>>>(ln2_g, ln2_b, out);
}

// round 5
// speedup vs baseline: 1.5018x; 1.4996x over previous
#include <cuda_runtime.h>
#include <math.h>
#include <stdint.h>

namespace {

constexpr int Bb  = 8;
constexpr int Hh  = 112;
constexpr int Ww  = 112;
constexpr int C   = 192;
constexpr int NH  = 6;
constexpr int HD  = 32;      // C / NH
constexpr int WS  = 7;
constexpr int SS  = 3;
constexpr int N   = 49;      // WS*WS
constexpr int WG  = Hh / WS; // 16
constexpr int NW  = WG * WG; // 256
constexpr int BW  = Bb * NW; // 2048
constexpr int T   = BW * N;  // 100352 tokens
constexpr int C4  = 4 * C;   // 768
constexpr float EPS    = 1e-5f;
constexpr float LOG100 = 4.605170185988091f;

// ---------------- scratch (static device globals; no allocation) -----------
__device__ float g_win [(size_t)T * C];   // gathered windows; later attn output
__device__ float g_q   [(size_t)T * C];   // q; later proj output
__device__ float g_k   [(size_t)T * C];   // k; later hidden
__device__ float g_v   [(size_t)T * C];   // v; later mlp output
__device__ float g_mlp1[(size_t)T * C4];  // fc1 output
__device__ float g_cpb [169 * NH];        // CPB MLP output table (169 x NH)
__device__ float g_scl [NH];              // per-head logit scale

// ---------------- CPB bias table MLP: (169,2)->512(relu)->NH ---------------
__global__ void cpb_kernel(const float* __restrict__ w0, const float* __restrict__ b0,
                           const float* __restrict__ w1, const float* __restrict__ ls) {
    int r   = blockIdx.x;     // 0..168
    int tid = threadIdx.x;    // 256 threads
    __shared__ float part[256][NH];

    int ri = r / 13, rj = r % 13;
    float t0 = (ri - 6) * (8.0f / 6.0f);
    float t1 = (rj - 6) * (8.0f / 6.0f);
    float v0 = copysignf(log2f(fabsf(t0) + 1.0f) * (1.0f / 3.0f), t0);
    float v1 = copysignf(log2f(fabsf(t1) + 1.0f) * (1.0f / 3.0f), t1);

    float acc[NH];
    #pragma unroll
    for (int h = 0; h < NH; ++h) acc[h] = 0.0f;
    for (int j = tid; j < 512; j += 256) {
        float hv = fmaxf(v0 * w0[j] + v1 * w0[512 + j] + b0[j], 0.0f);
        #pragma unroll
        for (int h = 0; h < NH; ++h) acc[h] += hv * w1[j * NH + h];
    }
    #pragma unroll
    for (int h = 0; h < NH; ++h) part[tid][h] = acc[h];
    __syncthreads();
    if (tid < NH) {
        float s = 0.0f;
        for (int i = 0; i < 256; ++i) s += part[i][tid];
        g_cpb[r * NH + tid] = s;
        if (r == 0) g_scl[tid] = expf(fminf(ls[tid], LOG100));
    }
}

// ---------------- cyclic shift + window partition gather -------------------
__global__ void gather_kernel(const float* __restrict__ x) {
    int t  = blockIdx.x;          // window-layout token
    int bw = t / N, n = t % N;
    int b  = bw / NW, w_ = bw % NW;
    int wy = w_ / WG, wx = w_ % WG;
    int hh = wy * WS + n / WS, ww = wx * WS + n % WS;
    int oh = (hh + SS) % Hh, ow = (ww + SS) % Ww;
    size_t src = ((size_t)(b * Hh + oh) * Ww + ow) * C;
    g_win[(size_t)t * C + threadIdx.x] = x[src + threadIdx.x];
}

// ---------------- TF32 tensor-core GEMM: C = act(A@B + bias) ---------------
// A: MxK row-major fp32, B: KxN row-major fp32. M%128==0, N%64==0, K%16==0.
// BM=128, BN=64, BK=16. 4 warps; warp tile 64x32; mma.m16n8k8.tf32.
constexpr int GBM = 128, GBN = 64, GBK = 16;
constexpr int APAD = 8, BPAD = 8;

__device__ __forceinline__ uint32_t f2tf32(float x) {
    uint32_t r;
    asm("cvt.rna.tf32.f32 %0, %1;" : "=r"(r) : "f"(x));
    return r;
}

__device__ __forceinline__ float gelu_tanh(float v) {
    return 0.5f * v * (1.0f + tanhf(0.7978845608028654f * (v + 0.044715f * v * v * v)));
}

__device__ __forceinline__ void mma_tf32(float* d, const uint32_t* a, const uint32_t* b) {
    asm volatile(
        "mma.sync.aligned.m16n8k8.row.col.f32.tf32.tf32.f32 "
        "{%0,%1,%2,%3},{%4,%5,%6,%7},{%8,%9},{%0,%1,%2,%3};"
        : "+f"(d[0]), "+f"(d[1]), "+f"(d[2]), "+f"(d[3])
        : "r"(a[0]), "r"(a[1]), "r"(a[2]), "r"(a[3]), "r"(b[0]), "r"(b[1]));
}

__global__ __launch_bounds__(128)
void tf32gemm_kernel(const float* __restrict__ A, const float* __restrict__ B,
                     const float* __restrict__ bias, float* __restrict__ Cmat,
                     int M, int Nn, int K, int act) {
    __shared__ uint32_t As[GBK][GBM + APAD];  // As[k][row], tf32 bits
    __shared__ uint32_t Bs[GBK][GBN + BPAD];  // Bs[k][col], tf32 bits

    int tid  = threadIdx.x;            // 0..127
    int lane = tid & 31;
    int warp = tid >> 5;               // 0..3
    int gid  = lane >> 2;              // 0..7
    int tg   = lane & 3;               // 0..3
    int bm = blockIdx.y * GBM;
    int bn = blockIdx.x * GBN;
    int warp_m = (warp >> 1) * 64;     // 0 or 64
    int warp_n = (warp & 1) * 32;      // 0 or 32

    float acc[4][4][4];
    #pragma unroll
    for (int mt = 0; mt < 4; ++mt)
        #pragma unroll
        for (int nt = 0; nt < 4; ++nt)
            #pragma unroll
            for (int e = 0; e < 4; ++e) acc[mt][nt][e] = 0.0f;

    for (int kt = 0; kt < K; kt += GBK) {
        // A tile: 128 rows x 16 k = 512 float4; 4 per thread
        #pragma unroll
        for (int i = 0; i < 4; ++i) {
            int idx = tid + i * 128;           // float4 index
            int row = idx >> 2;                // 16k = 4 float4/row
            int k4  = (idx & 3) * 4;
            float4 a = *reinterpret_cast<const float4*>(
                &A[(size_t)(bm + row) * K + kt + k4]);
            As[k4 + 0][row] = f2tf32(a.x);
            As[k4 + 1][row] = f2tf32(a.y);
            As[k4 + 2][row] = f2tf32(a.z);
            As[k4 + 3][row] = f2tf32(a.w);
        }
        // B tile: 16 k x 64 n = 256 float4; 2 per thread
        #pragma unroll
        for (int i = 0; i < 2; ++i) {
            int idx = tid + i * 128;
            int row = idx >> 4;                // 64n = 16 float4/row
            int c4  = (idx & 15) * 4;
            float4 b = *reinterpret_cast<const float4*>(
                &B[(size_t)(kt + row) * Nn + bn + c4]);
            Bs[row][c4 + 0] = f2tf32(b.x);
            Bs[row][c4 + 1] = f2tf32(b.y);
            Bs[row][c4 + 2] = f2tf32(b.z);
            Bs[row][c4 + 3] = f2tf32(b.w);
        }
        __syncthreads();

        #pragma unroll
        for (int ks = 0; ks < GBK; ks += 8) {
            uint32_t af[4][4];
            #pragma unroll
            for (int mt = 0; mt < 4; ++mt) {
                int r0 = warp_m + mt * 16 + gid;
                af[mt][0] = As[ks + tg    ][r0];
                af[mt][1] = As[ks + tg    ][r0 + 8];
                af[mt][2] = As[ks + tg + 4][r0];
                af[mt][3] = As[ks + tg + 4][r0 + 8];
            }
            uint32_t bf[4][2];
            #pragma unroll
            for (int nt = 0; nt < 4; ++nt) {
                int c0 = warp_n + nt * 8 + gid;
                bf[nt][0] = Bs[ks + tg    ][c0];
                bf[nt][1] = Bs[ks + tg + 4][c0];
            }
            #pragma unroll
            for (int mt = 0; mt < 4; ++mt)
                #pragma unroll
                for (int nt = 0; nt < 4; ++nt)
                    mma_tf32(acc[mt][nt], af[mt], bf[nt]);
        }
        __syncthreads();
    }

    // epilogue: bias + optional GELU, float2 stores (col even)
    #pragma unroll
    for (int mt = 0; mt < 4; ++mt) {
        #pragma unroll
        for (int r2 = 0; r2 < 2; ++r2) {
            int row = bm + warp_m + mt * 16 + gid + r2 * 8;
            #pragma unroll
            for (int nt = 0; nt < 4; ++nt) {
                int col = bn + warp_n + nt * 8 + tg * 2;
                float v0 = acc[mt][nt][r2 * 2 + 0];
                float v1 = acc[mt][nt][r2 * 2 + 1];
                if (bias) { v0 += bias[col]; v1 += bias[col + 1]; }
                if (act == 1) { v0 = gelu_tanh(v0); v1 = gelu_tanh(v1); }
                *reinterpret_cast<float2*>(&Cmat[(size_t)row * Nn + col]) =
                    make_float2(v0, v1);
            }
        }
    }
}

// ---------------- fused per-(window,head) attention -------------------------
__global__ __launch_bounds__(256)
void attn_kernel() {
    int blk = blockIdx.x;          // 0..BW*NH-1
    int bw  = blk / NH, h = blk % NH;
    int tid = threadIdx.x;

    __shared__ float qs[N * HD], ks[N * HD], vs[N * HD];
    __shared__ float lg[N * N];
    __shared__ int   rgn[N];
    __shared__ float scale_s;

    if (tid == 0) scale_s = g_scl[h];

    for (int e = tid; e < N * HD; e += blockDim.x) {
        int n = e / HD, d = e % HD;
        size_t base = (size_t)(bw * N + n) * C + h * HD + d;
        qs[e] = g_q[base]; ks[e] = g_k[base]; vs[e] = g_v[base];
    }
    if (tid < N) {
        int w_ = bw % NW, wy = w_ / WG, wx = w_ % WG;
        int gh = wy * WS + tid / WS, gw = wx * WS + tid % WS;
        int rh = gh < Hh - WS ? 0 : (gh < Hh - SS ? 1 : 2);
        int rw = gw < Ww - WS ? 0 : (gw < Ww - SS ? 1 : 2);
        rgn[tid] = rh * 3 + rw;
    }
    __syncthreads();

    // cosine-normalize rows (q also absorbs the logit scale)
    if (tid < 2 * N) {
        float* arr = (tid < N) ? qs : ks;
        int r = (tid < N) ? tid : tid - N;
        float ssum = 0.0f;
        #pragma unroll
        for (int d = 0; d < HD; ++d) { float u = arr[r * HD + d]; ssum += u * u; }
        float inv = 1.0f / fmaxf(sqrtf(ssum), 1e-12f);
        if (tid < N) inv *= scale_s;
        #pragma unroll
        for (int d = 0; d < HD; ++d) arr[r * HD + d] *= inv;
    }
    __syncthreads();

    // logits + CPB bias + shift mask
    for (int l = tid; l < N * N; l += blockDim.x) {
        int i = l / N, j = l % N;
        float dot = 0.0f;
        #pragma unroll
        for (int d = 0; d < HD; ++d) dot += qs[i * HD + d] * ks[j * HD + d];
        int idx = ((i / WS - j / WS) + WS - 1) * (2 * WS - 1)
                + ((i % WS - j % WS) + WS - 1);
        float b = g_cpb[idx * NH + h];
        float sig = 16.0f / (1.0f + __expf(-b));
        float m = (rgn[i] != rgn[j]) ? -100.0f : 0.0f;
        lg[l] = dot + sig + m;
    }
    __syncthreads();

    // row softmax
    if (tid < N) {
        float mx = -1e30f;
        for (int j = 0; j < N; ++j) mx = fmaxf(mx, lg[tid * N + j]);
        float s = 0.0f;
        for (int j = 0; j < N; ++j) {
            float e = __expf(lg[tid * N + j] - mx);
            lg[tid * N + j] = e; s += e;
        }
        float inv = 1.0f / s;
        for (int j = 0; j < N; ++j) lg[tid * N + j] *= inv;
    }
    __syncthreads();

    // out = attn @ v  -> write into g_win (window layout, head-interleaved)
    for (int e = tid; e < N * HD; e += blockDim.x) {
        int i = e / HD, d = e % HD;
        float a = 0.0f;
        #pragma unroll
        for (int j = 0; j < N; ++j) a += lg[i * N + j] * vs[j * HD + d];
        g_win[(size_t)(bw * N + i) * C + h * HD + d] = a;
    }
}

// ---------------- block-wide sum over 192 threads ---------------------------
__device__ __forceinline__ float block_sum192(float v, float* red) {
    #pragma unroll
    for (int o = 16; o > 0; o >>= 1) v += __shfl_down_sync(0xffffffffu, v, o);
    int wid = threadIdx.x >> 5;
    if ((threadIdx.x & 31) == 0) red[wid] = v;
    __syncthreads();
    float s = red[0] + red[1] + red[2] + red[3] + red[4] + red[5];
    __syncthreads();
    return s;
}

// hidden[dst] = x[dst] + LN1(proj[t]), with window-reverse + un-shift scatter
__global__ __launch_bounds__(192)
void postattn_kernel(const float* __restrict__ x,
                     const float* __restrict__ g1, const float* __restrict__ b1) {
    __shared__ float red[6];
    int t = blockIdx.x, c = threadIdx.x;
    int bw = t / N, n = t % N;
    int b  = bw / NW, w_ = bw % NW;
    int wy = w_ / WG, wx = w_ % WG;
    int hh = wy * WS + n / WS, ww = wx * WS + n % WS;
    int oh = (hh + SS) % Hh, ow = (ww + SS) % Ww;
    size_t dst = ((size_t)(b * Hh + oh) * Ww + ow) * C;

    float v = g_q[(size_t)t * C + c];          // proj output row
    float mean = block_sum192(v, red) * (1.0f / C);
    float dv = v - mean;
    float var = block_sum192(dv * dv, red) * (1.0f / C);
    float ln = dv * rsqrtf(var + EPS) * g1[c] + b1[c];
    g_k[dst + c] = x[dst + c] + ln;            // hidden (natural layout)
}

// out[t] = hidden[t] + LN2(mlp[t])
__global__ __launch_bounds__(192)
void final_kernel(const float* __restrict__ g2, const float* __restrict__ b2,
                  float* __restrict__ out) {
    __shared__ float red[6];
    int t = blockIdx.x, c = threadIdx.x;
    float v = g_v[(size_t)t * C + c];          // mlp output row
    float mean = block_sum192(v, red) * (1.0f / C);
    float dv = v - mean;
    float var = block_sum192(dv * dv, red) * (1.0f / C);
    float ln = dv * rsqrtf(var + EPS) * g2[c] + b2[c];
    out[(size_t)t * C + c] = g_k[(size_t)t * C + c] + ln;
}

} // namespace

// ============================================================================
extern "C" void kernel_launch(void* const* d_in, const int* in_sizes, int n_in,
                              void* d_out, int out_size) {
    const float* x      = (const float*)d_in[0];
    const float* ln1_g  = (const float*)d_in[1];
    const float* ln1_b  = (const float*)d_in[2];
    const float* ln2_g  = (const float*)d_in[3];
    const float* ln2_b  = (const float*)d_in[4];
    const float* q_w    = (const float*)d_in[5];
    const float* q_b    = (const float*)d_in[6];
    const float* k_w    = (const float*)d_in[7];
    const float* v_w    = (const float*)d_in[8];
    const float* v_b    = (const float*)d_in[9];
    const float* p_w    = (const float*)d_in[10];
    const float* p_b    = (const float*)d_in[11];
    const float* lscale = (const float*)d_in[12];
    const float* cpb_w0 = (const float*)d_in[13];
    const float* cpb_b0 = (const float*)d_in[14];
    const float* cpb_w1 = (const float*)d_in[15];
    const float* fc1_w  = (const float*)d_in[16];
    const float* fc1_b  = (const float*)d_in[17];
    const float* fc2_w  = (const float*)d_in[18];
    const float* fc2_b  = (const float*)d_in[19];
    float* out = (float*)d_out;

    float *p_win, *p_q, *p_k, *p_v, *p_m1;
    cudaGetSymbolAddress((void**)&p_win, g_win);
    cudaGetSymbolAddress((void**)&p_q,   g_q);
    cudaGetSymbolAddress((void**)&p_k,   g_k);
    cudaGetSymbolAddress((void**)&p_v,   g_v);
    cudaGetSymbolAddress((void**)&p_m1,  g_mlp1);

    // 1) CPB bias table + head scales
    cpb_kernel<<<169, 256>>>(cpb_w0, cpb_b0, cpb_w1, lscale);

    // 2) cyclic shift + window partition
    gather_kernel<<<T, C>>>(x);

    // 3-5) QKV GEMMs (win @ W [+ b])  — TF32 tensor cores
    dim3 gC(C / GBN, T / GBM);
    tf32gemm_kernel<<<gC, 128>>>(p_win, q_w, q_b,     p_q, T, C, C, 0);
    tf32gemm_kernel<<<gC, 128>>>(p_win, k_w, nullptr, p_k, T, C, C, 0);
    tf32gemm_kernel<<<gC, 128>>>(p_win, v_w, v_b,     p_v, T, C, C, 0);

    // 6) fused attention (writes attn output into g_win)
    attn_kernel<<<BW * NH, 256>>>();

    // 7) output projection
    tf32gemm_kernel<<<gC, 128>>>(p_win, p_w, p_b, p_q, T, C, C, 0);

    // 8) window reverse + un-shift + LN1 + residual -> hidden (g_k)
    postattn_kernel<<<T, C>>>(x, ln1_g, ln1_b);

    // 9) fc1 + GELU
    dim3 gF1(C4 / GBN, T / GBM);
    tf32gemm_kernel<<<gF1, 128>>>(p_k, fc1_w, fc1_b, p_m1, T, C4, C, 1);

    // 10) fc2
    tf32gemm_kernel<<<gC, 128>>>(p_m1, fc2_w, fc2_b, p_v, T, C, C4, 0);

    // 11) hidden + LN2(mlp) -> out
    final_kernel<<<T, C>>>(ln2_g, ln2_b, out);
}

// round 6
// speedup vs baseline: 1.5301x; 1.0189x over previous
#include <cuda_runtime.h>
#include <math.h>
#include <stdint.h>

namespace {

constexpr int Bb  = 8;
constexpr int Hh  = 112;
constexpr int Ww  = 112;
constexpr int C   = 192;
constexpr int NH  = 6;
constexpr int HD  = 32;      // C / NH
constexpr int WS  = 7;
constexpr int SS  = 3;
constexpr int N   = 49;      // WS*WS
constexpr int WG  = Hh / WS; // 16
constexpr int NW  = WG * WG; // 256
constexpr int BW  = Bb * NW; // 2048
constexpr int T   = BW * N;  // 100352 tokens
constexpr int C4  = 4 * C;   // 768
constexpr int QKVC = 3 * C;  // 576
constexpr float EPS    = 1e-5f;
constexpr float LOG100 = 4.605170185988091f;

// ---------------- scratch (static device globals; no allocation) -----------
__device__ float g_qkv [(size_t)T * QKVC]; // fused q|k|v (window-token layout)
__device__ float g_win [(size_t)T * C];    // attn output (window layout)
__device__ float g_q   [(size_t)T * C];    // proj output
__device__ float g_k   [(size_t)T * C];    // hidden (natural layout)
__device__ float g_v   [(size_t)T * C];    // mlp output
__device__ float g_mlp1[(size_t)T * C4];   // fc1 output
__device__ float g_wqkv[C * QKVC];         // packed qkv weight (192 x 576)
__device__ float g_bqkv[QKVC];             // packed qkv bias
__device__ float g_cpb [169 * NH];         // CPB MLP output table (169 x NH)
__device__ float g_scl [NH];               // per-head logit scale

// ---------------- CPB bias table MLP: (169,2)->512(relu)->NH ---------------
__global__ void cpb_kernel(const float* __restrict__ w0, const float* __restrict__ b0,
                           const float* __restrict__ w1, const float* __restrict__ ls) {
    int r   = blockIdx.x;     // 0..168
    int tid = threadIdx.x;    // 256 threads
    __shared__ float part[256][NH];

    int ri = r / 13, rj = r % 13;
    float t0 = (ri - 6) * (8.0f / 6.0f);
    float t1 = (rj - 6) * (8.0f / 6.0f);
    float v0 = copysignf(log2f(fabsf(t0) + 1.0f) * (1.0f / 3.0f), t0);
    float v1 = copysignf(log2f(fabsf(t1) + 1.0f) * (1.0f / 3.0f), t1);

    float acc[NH];
    #pragma unroll
    for (int h = 0; h < NH; ++h) acc[h] = 0.0f;
    for (int j = tid; j < 512; j += 256) {
        float hv = fmaxf(v0 * w0[j] + v1 * w0[512 + j] + b0[j], 0.0f);
        #pragma unroll
        for (int h = 0; h < NH; ++h) acc[h] += hv * w1[j * NH + h];
    }
    #pragma unroll
    for (int h = 0; h < NH; ++h) part[tid][h] = acc[h];
    __syncthreads();
    if (tid < NH) {
        float s = 0.0f;
        for (int i = 0; i < 256; ++i) s += part[i][tid];
        g_cpb[r * NH + tid] = s;
        if (r == 0) g_scl[tid] = expf(fminf(ls[tid], LOG100));
    }
}

// ---------------- pack q|k|v weights + bias into one matrix ----------------
__global__ void packqkv_kernel(const float* __restrict__ qw, const float* __restrict__ kw,
                               const float* __restrict__ vw, const float* __restrict__ qb,
                               const float* __restrict__ vb) {
    int k = blockIdx.x;          // 0..191
    int j = threadIdx.x;         // 0..575
    float w;
    if (j < C)            w = qw[k * C + j];
    else if (j < 2 * C)   w = kw[k * C + (j - C)];
    else                  w = vw[k * C + (j - 2 * C)];
    g_wqkv[k * QKVC + j] = w;
    if (k == 0) {
        float b;
        if (j < C)          b = qb[j];
        else if (j < 2 * C) b = 0.0f;
        else                b = vb[j - 2 * C];
        g_bqkv[j] = b;
    }
}

// ---------------- TF32 tensor-core GEMM: C = act(A@B + bias) ---------------
// A: MxK row-major fp32 (optionally row-gathered), B: KxN row-major fp32.
// M%128==0, N%64==0, K%16==0. 4 warps, warp tile 64x32, mma.m16n8k8.tf32,
// register-staged double buffering of the gmem loads.
constexpr int GBM = 128, GBN = 64, GBK = 16;
constexpr int APAD = 8, BPAD = 8;

__device__ __forceinline__ uint32_t f2tf32(float x) {
    uint32_t r;
    asm("cvt.rna.tf32.f32 %0, %1;" : "=r"(r) : "f"(x));
    return r;
}

__device__ __forceinline__ float gelu_tanh(float v) {
    return 0.5f * v * (1.0f + tanhf(0.7978845608028654f * (v + 0.044715f * v * v * v)));
}

__device__ __forceinline__ void mma_tf32(float* d, const uint32_t* a, const uint32_t* b) {
    asm volatile(
        "mma.sync.aligned.m16n8k8.row.col.f32.tf32.tf32.f32 "
        "{%0,%1,%2,%3},{%4,%5,%6,%7},{%8,%9},{%0,%1,%2,%3};"
        : "+f"(d[0]), "+f"(d[1]), "+f"(d[2]), "+f"(d[3])
        : "r"(a[0]), "r"(a[1]), "r"(a[2]), "r"(a[3]), "r"(b[0]), "r"(b[1]));
}

__global__ __launch_bounds__(128)
void tf32gemm_kernel(const float* __restrict__ A, const float* __restrict__ B,
                     const float* __restrict__ bias, float* __restrict__ Cmat,
                     int M, int Nn, int K, int act, int gatherA) {
    __shared__ uint32_t As[GBK][GBM + APAD];  // As[k][row], tf32 bits
    __shared__ uint32_t Bs[GBK][GBN + BPAD];  // Bs[k][col], tf32 bits

    int tid  = threadIdx.x;            // 0..127
    int lane = tid & 31;
    int warp = tid >> 5;               // 0..3
    int gid  = lane >> 2;              // 0..7
    int tg   = lane & 3;               // 0..3
    int bm = blockIdx.y * GBM;
    int bn = blockIdx.x * GBN;
    int warp_m = (warp >> 1) * 64;     // 0 or 64
    int warp_n = (warp & 1) * 32;      // 0 or 32

    // per-thread fixed source rows for the A tile (4 float4 per K-tile)
    const float* aSrc[4];
    int aRow[4], aK4[4];
    #pragma unroll
    for (int i = 0; i < 4; ++i) {
        int idx = tid + i * 128;        // float4 index within 128x16 tile
        int row = idx >> 2;
        aRow[i] = row;
        aK4[i]  = (idx & 3) * 4;
        int r = bm + row;
        size_t abase;
        if (gatherA) {
            int bw = r / N, n = r % N;
            int b  = bw / NW, w_ = bw % NW;
            int wy = w_ / WG, wx = w_ % WG;
            int hh = wy * WS + n / WS, ww = wx * WS + n % WS;
            int oh = (hh + SS) % Hh, ow = (ww + SS) % Ww;
            abase = ((size_t)(b * Hh + oh) * Ww + ow) * (size_t)K;
        } else {
            abase = (size_t)r * K;
        }
        aSrc[i] = A + abase + aK4[i];
    }
    int bRow[2], bC4[2];
    #pragma unroll
    for (int i = 0; i < 2; ++i) {
        int idx = tid + i * 128;
        bRow[i] = idx >> 4;
        bC4[i]  = (idx & 15) * 4;
    }

    float acc[4][4][4];
    #pragma unroll
    for (int mt = 0; mt < 4; ++mt)
        #pragma unroll
        for (int nt = 0; nt < 4; ++nt)
            #pragma unroll
            for (int e = 0; e < 4; ++e) acc[mt][nt][e] = 0.0f;

    float4 aReg[4], bReg[2];
    // prologue: load K-tile 0
    #pragma unroll
    for (int i = 0; i < 4; ++i)
        aReg[i] = *reinterpret_cast<const float4*>(aSrc[i]);
    #pragma unroll
    for (int i = 0; i < 2; ++i)
        bReg[i] = *reinterpret_cast<const float4*>(&B[(size_t)bRow[i] * Nn + bn + bC4[i]]);

    for (int kt = 0; kt < K; kt += GBK) {
        // stage current tile into smem (cvt to tf32)
        #pragma unroll
        for (int i = 0; i < 4; ++i) {
            As[aK4[i] + 0][aRow[i]] = f2tf32(aReg[i].x);
            As[aK4[i] + 1][aRow[i]] = f2tf32(aReg[i].y);
            As[aK4[i] + 2][aRow[i]] = f2tf32(aReg[i].z);
            As[aK4[i] + 3][aRow[i]] = f2tf32(aReg[i].w);
        }
        #pragma unroll
        for (int i = 0; i < 2; ++i) {
            Bs[bRow[i]][bC4[i] + 0] = f2tf32(bReg[i].x);
            Bs[bRow[i]][bC4[i] + 1] = f2tf32(bReg[i].y);
            Bs[bRow[i]][bC4[i] + 2] = f2tf32(bReg[i].z);
            Bs[bRow[i]][bC4[i] + 3] = f2tf32(bReg[i].w);
        }
        __syncthreads();

        // prefetch next tile into registers (overlaps with compute below)
        if (kt + GBK < K) {
            #pragma unroll
            for (int i = 0; i < 4; ++i)
                aReg[i] = *reinterpret_cast<const float4*>(aSrc[i] + kt + GBK);
            #pragma unroll
            for (int i = 0; i < 2; ++i)
                bReg[i] = *reinterpret_cast<const float4*>(
                    &B[(size_t)(kt + GBK + bRow[i]) * Nn + bn + bC4[i]]);
        }

        #pragma unroll
        for (int ks = 0; ks < GBK; ks += 8) {
            uint32_t af[4][4];
            #pragma unroll
            for (int mt = 0; mt < 4; ++mt) {
                int r0 = warp_m + mt * 16 + gid;
                af[mt][0] = As[ks + tg    ][r0];
                af[mt][1] = As[ks + tg    ][r0 + 8];
                af[mt][2] = As[ks + tg + 4][r0];
                af[mt][3] = As[ks + tg + 4][r0 + 8];
            }
            uint32_t bf[4][2];
            #pragma unroll
            for (int nt = 0; nt < 4; ++nt) {
                int c0 = warp_n + nt * 8 + gid;
                bf[nt][0] = Bs[ks + tg    ][c0];
                bf[nt][1] = Bs[ks + tg + 4][c0];
            }
            #pragma unroll
            for (int mt = 0; mt < 4; ++mt)
                #pragma unroll
                for (int nt = 0; nt < 4; ++nt)
                    mma_tf32(acc[mt][nt], af[mt], bf[nt]);
        }
        __syncthreads();
    }

    // epilogue: bias + optional GELU, float2 stores (col even)
    #pragma unroll
    for (int mt = 0; mt < 4; ++mt) {
        #pragma unroll
        for (int r2 = 0; r2 < 2; ++r2) {
            int row = bm + warp_m + mt * 16 + gid + r2 * 8;
            #pragma unroll
            for (int nt = 0; nt < 4; ++nt) {
                int col = bn + warp_n + nt * 8 + tg * 2;
                float v0 = acc[mt][nt][r2 * 2 + 0];
                float v1 = acc[mt][nt][r2 * 2 + 1];
                if (bias) { v0 += bias[col]; v1 += bias[col + 1]; }
                if (act == 1) { v0 = gelu_tanh(v0); v1 = gelu_tanh(v1); }
                *reinterpret_cast<float2*>(&Cmat[(size_t)row * Nn + col]) =
                    make_float2(v0, v1);
            }
        }
    }
}

// ---------------- fused per-(window,head) attention -------------------------
__global__ __launch_bounds__(256)
void attn_kernel() {
    int blk = blockIdx.x;          // 0..BW*NH-1
    int bw  = blk / NH, h = blk % NH;
    int tid = threadIdx.x;

    __shared__ float qs[N * HD], ks[N * HD], vs[N * HD];
    __shared__ float lg[N * N];
    __shared__ int   rgn[N];
    __shared__ float scale_s;

    if (tid == 0) scale_s = g_scl[h];

    for (int e = tid; e < N * HD; e += blockDim.x) {
        int n = e / HD, d = e % HD;
        size_t base = (size_t)(bw * N + n) * QKVC + h * HD + d;
        qs[e] = g_qkv[base];
        ks[e] = g_qkv[base + C];
        vs[e] = g_qkv[base + 2 * C];
    }
    if (tid < N) {
        int w_ = bw % NW, wy = w_ / WG, wx = w_ % WG;
        int gh = wy * WS + tid / WS, gw = wx * WS + tid % WS;
        int rh = gh < Hh - WS ? 0 : (gh < Hh - SS ? 1 : 2);
        int rw = gw < Ww - WS ? 0 : (gw < Ww - SS ? 1 : 2);
        rgn[tid] = rh * 3 + rw;
    }
    __syncthreads();

    // cosine-normalize rows (q also absorbs the logit scale)
    if (tid < 2 * N) {
        float* arr = (tid < N) ? qs : ks;
        int r = (tid < N) ? tid : tid - N;
        float ssum = 0.0f;
        #pragma unroll
        for (int d = 0; d < HD; ++d) { float u = arr[r * HD + d]; ssum += u * u; }
        float inv = 1.0f / fmaxf(sqrtf(ssum), 1e-12f);
        if (tid < N) inv *= scale_s;
        #pragma unroll
        for (int d = 0; d < HD; ++d) arr[r * HD + d] *= inv;
    }
    __syncthreads();

    // logits + CPB bias + shift mask
    for (int l = tid; l < N * N; l += blockDim.x) {
        int i = l / N, j = l % N;
        float dot = 0.0f;
        #pragma unroll
        for (int d = 0; d < HD; ++d) dot += qs[i * HD + d] * ks[j * HD + d];
        int idx = ((i / WS - j / WS) + WS - 1) * (2 * WS - 1)
                + ((i % WS - j % WS) + WS - 1);
        float b = g_cpb[idx * NH + h];
        float sig = 16.0f / (1.0f + __expf(-b));
        float m = (rgn[i] != rgn[j]) ? -100.0f : 0.0f;
        lg[l] = dot + sig + m;
    }
    __syncthreads();

    // row softmax
    if (tid < N) {
        float mx = -1e30f;
        for (int j = 0; j < N; ++j) mx = fmaxf(mx, lg[tid * N + j]);
        float s = 0.0f;
        for (int j = 0; j < N; ++j) {
            float e = __expf(lg[tid * N + j] - mx);
            lg[tid * N + j] = e; s += e;
        }
        float inv = 1.0f / s;
        for (int j = 0; j < N; ++j) lg[tid * N + j] *= inv;
    }
    __syncthreads();

    // out = attn @ v  -> write into g_win (window layout, head-interleaved)
    for (int e = tid; e < N * HD; e += blockDim.x) {
        int i = e / HD, d = e % HD;
        float a = 0.0f;
        #pragma unroll
        for (int j = 0; j < N; ++j) a += lg[i * N + j] * vs[j * HD + d];
        g_win[(size_t)(bw * N + i) * C + h * HD + d] = a;
    }
}

// ---------------- block-wide sum over 192 threads ---------------------------
__device__ __forceinline__ float block_sum192(float v, float* red) {
    #pragma unroll
    for (int o = 16; o > 0; o >>= 1) v += __shfl_down_sync(0xffffffffu, v, o);
    int wid = threadIdx.x >> 5;
    if ((threadIdx.x & 31) == 0) red[wid] = v;
    __syncthreads();
    float s = red[0] + red[1] + red[2] + red[3] + red[4] + red[5];
    __syncthreads();
    return s;
}

// hidden[dst] = x[dst] + LN1(proj[t]), with window-reverse + un-shift scatter
__global__ __launch_bounds__(192)
void postattn_kernel(const float* __restrict__ x,
                     const float* __restrict__ g1, const float* __restrict__ b1) {
    __shared__ float red[6];
    int t = blockIdx.x, c = threadIdx.x;
    int bw = t / N, n = t % N;
    int b  = bw / NW, w_ = bw % NW;
    int wy = w_ / WG, wx = w_ % WG;
    int hh = wy * WS + n / WS, ww = wx * WS + n % WS;
    int oh = (hh + SS) % Hh, ow = (ww + SS) % Ww;
    size_t dst = ((size_t)(b * Hh + oh) * Ww + ow) * C;

    float v = g_q[(size_t)t * C + c];          // proj output row
    float mean = block_sum192(v, red) * (1.0f / C);
    float dv = v - mean;
    float var = block_sum192(dv * dv, red) * (1.0f / C);
    float ln = dv * rsqrtf(var + EPS) * g1[c] + b1[c];
    g_k[dst + c] = x[dst + c] + ln;            // hidden (natural layout)
}

// out[t] = hidden[t] + LN2(mlp[t])
__global__ __launch_bounds__(192)
void final_kernel(const float* __restrict__ g2, const float* __restrict__ b2,
                  float* __restrict__ out) {
    __shared__ float red[6];
    int t = blockIdx.x, c = threadIdx.x;
    float v = g_v[(size_t)t * C + c];          // mlp output row
    float mean = block_sum192(v, red) * (1.0f / C);
    float dv = v - mean;
    float var = block_sum192(dv * dv, red) * (1.0f / C);
    float ln = dv * rsqrtf(var + EPS) * g2[c] + b2[c];
    out[(size_t)t * C + c] = g_k[(size_t)t * C + c] + ln;
}

} // namespace

// ============================================================================
extern "C" void kernel_launch(void* const* d_in, const int* in_sizes, int n_in,
                              void* d_out, int out_size) {
    const float* x      = (const float*)d_in[0];
    const float* ln1_g  = (const float*)d_in[1];
    const float* ln1_b  = (const float*)d_in[2];
    const float* ln2_g  = (const float*)d_in[3];
    const float* ln2_b  = (const float*)d_in[4];
    const float* q_w    = (const float*)d_in[5];
    const float* q_b    = (const float*)d_in[6];
    const float* k_w    = (const float*)d_in[7];
    const float* v_w    = (const float*)d_in[8];
    const float* v_b    = (const float*)d_in[9];
    const float* p_w    = (const float*)d_in[10];
    const float* p_b    = (const float*)d_in[11];
    const float* lscale = (const float*)d_in[12];
    const float* cpb_w0 = (const float*)d_in[13];
    const float* cpb_b0 = (const float*)d_in[14];
    const float* cpb_w1 = (const float*)d_in[15];
    const float* fc1_w  = (const float*)d_in[16];
    const float* fc1_b  = (const float*)d_in[17];
    const float* fc2_w  = (const float*)d_in[18];
    const float* fc2_b  = (const float*)d_in[19];
    float* out = (float*)d_out;

    float *p_qkv, *p_win, *p_q, *p_k, *p_v, *p_m1, *p_wqkv, *p_bqkv;
    cudaGetSymbolAddress((void**)&p_qkv,  g_qkv);
    cudaGetSymbolAddress((void**)&p_win,  g_win);
    cudaGetSymbolAddress((void**)&p_q,    g_q);
    cudaGetSymbolAddress((void**)&p_k,    g_k);
    cudaGetSymbolAddress((void**)&p_v,    g_v);
    cudaGetSymbolAddress((void**)&p_m1,   g_mlp1);
    cudaGetSymbolAddress((void**)&p_wqkv, g_wqkv);
    cudaGetSymbolAddress((void**)&p_bqkv, g_bqkv);

    // 1) CPB bias table + head scales; pack QKV weights
    cpb_kernel<<<169, 256>>>(cpb_w0, cpb_b0, cpb_w1, lscale);
    packqkv_kernel<<<C, QKVC>>>(q_w, k_w, v_w, q_b, v_b);

    // 2) fused shift+window-gather + QKV GEMM  (A = x with permuted rows)
    dim3 gQKV(QKVC / GBN, T / GBM);
    tf32gemm_kernel<<<gQKV, 128>>>(x, p_wqkv, p_bqkv, p_qkv, T, QKVC, C, 0, 1);

    // 3) fused attention (writes attn output into g_win)
    attn_kernel<<<BW * NH, 256>>>();

    // 4) output projection
    dim3 gC(C / GBN, T / GBM);
    tf32gemm_kernel<<<gC, 128>>>(p_win, p_w, p_b, p_q, T, C, C, 0, 0);

    // 5) window reverse + un-shift + LN1 + residual -> hidden (g_k)
    postattn_kernel<<<T, C>>>(x, ln1_g, ln1_b);

    // 6) fc1 + GELU
    dim3 gF1(C4 / GBN, T / GBM);
    tf32gemm_kernel<<<gF1, 128>>>(p_k, fc1_w, fc1_b, p_m1, T, C4, C, 1, 0);

    // 7) fc2
    tf32gemm_kernel<<<gC, 128>>>(p_m1, fc2_w, fc2_b, p_v, T, C, C4, 0, 0);

    // 8) hidden + LN2(mlp) -> out
    final_kernel<<<T, C>>>(ln2_g, ln2_b, out);
}

// round 7
// speedup vs baseline: 2.3803x; 1.5556x over previous
#include <cuda_runtime.h>
#include <math.h>
#include <stdint.h>

namespace {

constexpr int Bb  = 8;
constexpr int Hh  = 112;
constexpr int Ww  = 112;
constexpr int C   = 192;
constexpr int NH  = 6;
constexpr int HD  = 32;      // C / NH
constexpr int WS  = 7;
constexpr int SS  = 3;
constexpr int N   = 49;      // WS*WS
constexpr int WG  = Hh / WS; // 16
constexpr int NW  = WG * WG; // 256
constexpr int BW  = Bb * NW; // 2048
constexpr int T   = BW * N;  // 100352 tokens
constexpr int C4  = 4 * C;   // 768
constexpr int QKVC = 3 * C;  // 576
constexpr float EPS    = 1e-5f;
constexpr float LOG100 = 4.605170185988091f;

// ---------------- scratch (static device globals; no allocation) -----------
__device__ float g_qkv [(size_t)T * QKVC]; // fused q|k|v (window-token layout)
__device__ float g_win [(size_t)T * C];    // attn output (window layout)
__device__ float g_q   [(size_t)T * C];    // proj output
__device__ float g_k   [(size_t)T * C];    // hidden (natural layout)
__device__ float g_v   [(size_t)T * C];    // mlp output
__device__ float g_mlp1[(size_t)T * C4];   // fc1 output
__device__ float g_wqkv[C * QKVC];         // packed qkv weight (192 x 576)
__device__ float g_bqkv[QKVC];             // packed qkv bias
__device__ float g_cpb [169 * NH];         // CPB MLP output table (169 x NH)
__device__ float g_scl [NH];               // per-head logit scale

// ---------------- CPB bias table MLP: (169,2)->512(relu)->NH ---------------
__global__ void cpb_kernel(const float* __restrict__ w0, const float* __restrict__ b0,
                           const float* __restrict__ w1, const float* __restrict__ ls) {
    int r   = blockIdx.x;     // 0..168
    int tid = threadIdx.x;    // 256 threads
    __shared__ float part[256][NH];

    int ri = r / 13, rj = r % 13;
    float t0 = (ri - 6) * (8.0f / 6.0f);
    float t1 = (rj - 6) * (8.0f / 6.0f);
    float v0 = copysignf(log2f(fabsf(t0) + 1.0f) * (1.0f / 3.0f), t0);
    float v1 = copysignf(log2f(fabsf(t1) + 1.0f) * (1.0f / 3.0f), t1);

    float acc[NH];
    #pragma unroll
    for (int h = 0; h < NH; ++h) acc[h] = 0.0f;
    for (int j = tid; j < 512; j += 256) {
        float hv = fmaxf(v0 * w0[j] + v1 * w0[512 + j] + b0[j], 0.0f);
        #pragma unroll
        for (int h = 0; h < NH; ++h) acc[h] += hv * w1[j * NH + h];
    }
    #pragma unroll
    for (int h = 0; h < NH; ++h) part[tid][h] = acc[h];
    __syncthreads();
    if (tid < NH) {
        float s = 0.0f;
        for (int i = 0; i < 256; ++i) s += part[i][tid];
        g_cpb[r * NH + tid] = s;
        if (r == 0) g_scl[tid] = expf(fminf(ls[tid], LOG100));
    }
}

// ---------------- pack q|k|v weights + bias into one matrix ----------------
__global__ void packqkv_kernel(const float* __restrict__ qw, const float* __restrict__ kw,
                               const float* __restrict__ vw, const float* __restrict__ qb,
                               const float* __restrict__ vb) {
    int k = blockIdx.x;          // 0..191
    int j = threadIdx.x;         // 0..575
    float w;
    if (j < C)            w = qw[k * C + j];
    else if (j < 2 * C)   w = kw[k * C + (j - C)];
    else                  w = vw[k * C + (j - 2 * C)];
    g_wqkv[k * QKVC + j] = w;
    if (k == 0) {
        float b;
        if (j < C)          b = qb[j];
        else if (j < 2 * C) b = 0.0f;
        else                b = vb[j - 2 * C];
        g_bqkv[j] = b;
    }
}

// ---------------- TF32 tensor-core GEMM: C = act(A@B + bias) ---------------
constexpr int GBM = 128, GBN = 64, GBK = 16;
constexpr int APAD = 8, BPAD = 8;

__device__ __forceinline__ uint32_t f2tf32(float x) {
    uint32_t r;
    asm("cvt.rna.tf32.f32 %0, %1;" : "=r"(r) : "f"(x));
    return r;
}

__device__ __forceinline__ float gelu_tanh(float v) {
    return 0.5f * v * (1.0f + tanhf(0.7978845608028654f * (v + 0.044715f * v * v * v)));
}

__device__ __forceinline__ void mma_tf32(float* d, const uint32_t* a, const uint32_t* b) {
    asm volatile(
        "mma.sync.aligned.m16n8k8.row.col.f32.tf32.tf32.f32 "
        "{%0,%1,%2,%3},{%4,%5,%6,%7},{%8,%9},{%0,%1,%2,%3};"
        : "+f"(d[0]), "+f"(d[1]), "+f"(d[2]), "+f"(d[3])
        : "r"(a[0]), "r"(a[1]), "r"(a[2]), "r"(a[3]), "r"(b[0]), "r"(b[1]));
}

__global__ __launch_bounds__(128)
void tf32gemm_kernel(const float* __restrict__ A, const float* __restrict__ B,
                     const float* __restrict__ bias, float* __restrict__ Cmat,
                     int M, int Nn, int K, int act, int gatherA) {
    __shared__ uint32_t As[GBK][GBM + APAD];  // As[k][row], tf32 bits
    __shared__ uint32_t Bs[GBK][GBN + BPAD];  // Bs[k][col], tf32 bits

    int tid  = threadIdx.x;            // 0..127
    int lane = tid & 31;
    int warp = tid >> 5;               // 0..3
    int gid  = lane >> 2;              // 0..7
    int tg   = lane & 3;               // 0..3
    int bm = blockIdx.y * GBM;
    int bn = blockIdx.x * GBN;
    int warp_m = (warp >> 1) * 64;     // 0 or 64
    int warp_n = (warp & 1) * 32;      // 0 or 32

    const float* aSrc[4];
    int aRow[4], aK4[4];
    #pragma unroll
    for (int i = 0; i < 4; ++i) {
        int idx = tid + i * 128;        // float4 index within 128x16 tile
        int row = idx >> 2;
        aRow[i] = row;
        aK4[i]  = (idx & 3) * 4;
        int r = bm + row;
        size_t abase;
        if (gatherA) {
            int bw = r / N, n = r % N;
            int b  = bw / NW, w_ = bw % NW;
            int wy = w_ / WG, wx = w_ % WG;
            int hh = wy * WS + n / WS, ww = wx * WS + n % WS;
            int oh = (hh + SS) % Hh, ow = (ww + SS) % Ww;
            abase = ((size_t)(b * Hh + oh) * Ww + ow) * (size_t)K;
        } else {
            abase = (size_t)r * K;
        }
        aSrc[i] = A + abase + aK4[i];
    }
    int bRow[2], bC4[2];
    #pragma unroll
    for (int i = 0; i < 2; ++i) {
        int idx = tid + i * 128;
        bRow[i] = idx >> 4;
        bC4[i]  = (idx & 15) * 4;
    }

    float acc[4][4][4];
    #pragma unroll
    for (int mt = 0; mt < 4; ++mt)
        #pragma unroll
        for (int nt = 0; nt < 4; ++nt)
            #pragma unroll
            for (int e = 0; e < 4; ++e) acc[mt][nt][e] = 0.0f;

    float4 aReg[4], bReg[2];
    #pragma unroll
    for (int i = 0; i < 4; ++i)
        aReg[i] = *reinterpret_cast<const float4*>(aSrc[i]);
    #pragma unroll
    for (int i = 0; i < 2; ++i)
        bReg[i] = *reinterpret_cast<const float4*>(&B[(size_t)bRow[i] * Nn + bn + bC4[i]]);

    for (int kt = 0; kt < K; kt += GBK) {
        #pragma unroll
        for (int i = 0; i < 4; ++i) {
            As[aK4[i] + 0][aRow[i]] = f2tf32(aReg[i].x);
            As[aK4[i] + 1][aRow[i]] = f2tf32(aReg[i].y);
            As[aK4[i] + 2][aRow[i]] = f2tf32(aReg[i].z);
            As[aK4[i] + 3][aRow[i]] = f2tf32(aReg[i].w);
        }
        #pragma unroll
        for (int i = 0; i < 2; ++i) {
            Bs[bRow[i]][bC4[i] + 0] = f2tf32(bReg[i].x);
            Bs[bRow[i]][bC4[i] + 1] = f2tf32(bReg[i].y);
            Bs[bRow[i]][bC4[i] + 2] = f2tf32(bReg[i].z);
            Bs[bRow[i]][bC4[i] + 3] = f2tf32(bReg[i].w);
        }
        __syncthreads();

        if (kt + GBK < K) {
            #pragma unroll
            for (int i = 0; i < 4; ++i)
                aReg[i] = *reinterpret_cast<const float4*>(aSrc[i] + kt + GBK);
            #pragma unroll
            for (int i = 0; i < 2; ++i)
                bReg[i] = *reinterpret_cast<const float4*>(
                    &B[(size_t)(kt + GBK + bRow[i]) * Nn + bn + bC4[i]]);
        }

        #pragma unroll
        for (int ks = 0; ks < GBK; ks += 8) {
            uint32_t af[4][4];
            #pragma unroll
            for (int mt = 0; mt < 4; ++mt) {
                int r0 = warp_m + mt * 16 + gid;
                af[mt][0] = As[ks + tg    ][r0];
                af[mt][1] = As[ks + tg    ][r0 + 8];
                af[mt][2] = As[ks + tg + 4][r0];
                af[mt][3] = As[ks + tg + 4][r0 + 8];
            }
            uint32_t bf[4][2];
            #pragma unroll
            for (int nt = 0; nt < 4; ++nt) {
                int c0 = warp_n + nt * 8 + gid;
                bf[nt][0] = Bs[ks + tg    ][c0];
                bf[nt][1] = Bs[ks + tg + 4][c0];
            }
            #pragma unroll
            for (int mt = 0; mt < 4; ++mt)
                #pragma unroll
                for (int nt = 0; nt < 4; ++nt)
                    mma_tf32(acc[mt][nt], af[mt], bf[nt]);
        }
        __syncthreads();
    }

    #pragma unroll
    for (int mt = 0; mt < 4; ++mt) {
        #pragma unroll
        for (int r2 = 0; r2 < 2; ++r2) {
            int row = bm + warp_m + mt * 16 + gid + r2 * 8;
            #pragma unroll
            for (int nt = 0; nt < 4; ++nt) {
                int col = bn + warp_n + nt * 8 + tg * 2;
                float v0 = acc[mt][nt][r2 * 2 + 0];
                float v1 = acc[mt][nt][r2 * 2 + 1];
                if (bias) { v0 += bias[col]; v1 += bias[col + 1]; }
                if (act == 1) { v0 = gelu_tanh(v0); v1 = gelu_tanh(v1); }
                *reinterpret_cast<float2*>(&Cmat[(size_t)row * Nn + col]) =
                    make_float2(v0, v1);
            }
        }
    }
}

// ---------------- fused per-(window,head) attention (v2) --------------------
// 128 threads. Padded smem rows (stride 36), float4 everywhere, q cached in
// registers for logits, warp-per-row softmax with shuffles.
constexpr int SD = HD + 4;   // 36 floats: padded row stride for q/k/v
constexpr int LS = 52;       // padded row stride for logits

__global__ __launch_bounds__(128)
void attn_kernel() {
    int blk = blockIdx.x;          // 0..BW*NH-1
    int bw  = blk / NH, h = blk % NH;
    int tid = threadIdx.x;
    int warp = tid >> 5, lane = tid & 31;

    __shared__ float qs[N * SD], ks[N * SD], vs[N * SD];
    __shared__ float lg[N * LS];
    __shared__ int   rgn[N];
    __shared__ float scale_s;

    if (tid == 0) scale_s = g_scl[h];
    if (tid < N) {
        int w_ = bw % NW, wy = w_ / WG, wx = w_ % WG;
        int gh = wy * WS + tid / WS, gw = wx * WS + tid % WS;
        int rh = gh < Hh - WS ? 0 : (gh < Hh - SS ? 1 : 2);
        int rw = gw < Ww - WS ? 0 : (gw < Ww - SS ? 1 : 2);
        rgn[tid] = rh * 3 + rw;
    }

    // load q,k,v rows as float4
    const float* src = g_qkv + (size_t)bw * N * QKVC + h * HD;
    for (int e = tid; e < N * 8; e += 128) {
        int n = e >> 3, d4 = (e & 7) * 4;
        const float* row = src + (size_t)n * QKVC + d4;
        *reinterpret_cast<float4*>(&qs[n * SD + d4]) =
            *reinterpret_cast<const float4*>(row);
        *reinterpret_cast<float4*>(&ks[n * SD + d4]) =
            *reinterpret_cast<const float4*>(row + C);
        *reinterpret_cast<float4*>(&vs[n * SD + d4]) =
            *reinterpret_cast<const float4*>(row + 2 * C);
    }
    __syncthreads();

    // cosine-normalize rows (q also absorbs the logit scale)
    if (tid < 2 * N) {
        float* arr = (tid < N) ? qs : ks;
        int r = (tid < N) ? tid : tid - N;
        float ssum = 0.0f;
        #pragma unroll
        for (int d4 = 0; d4 < 8; ++d4) {
            float4 u = *reinterpret_cast<float4*>(&arr[r * SD + d4 * 4]);
            ssum += u.x * u.x + u.y * u.y + u.z * u.z + u.w * u.w;
        }
        float inv = 1.0f / fmaxf(sqrtf(ssum), 1e-12f);
        if (tid < N) inv *= scale_s;
        #pragma unroll
        for (int d4 = 0; d4 < 8; ++d4) {
            float4 u = *reinterpret_cast<float4*>(&arr[r * SD + d4 * 4]);
            u.x *= inv; u.y *= inv; u.z *= inv; u.w *= inv;
            *reinterpret_cast<float4*>(&arr[r * SD + d4 * 4]) = u;
        }
    }
    __syncthreads();

    // logits + CPB bias + shift mask. 2 threads per row; q row in registers.
    {
        int i = tid >> 1, p = tid & 1;
        if (i < N) {
            float4 qr[8];
            #pragma unroll
            for (int d4 = 0; d4 < 8; ++d4)
                qr[d4] = *reinterpret_cast<float4*>(&qs[i * SD + d4 * 4]);
            int iy = i / WS, ix = i % WS, ri = rgn[i];
            for (int j = p; j < N; j += 2) {
                float4 s4 = make_float4(0.f, 0.f, 0.f, 0.f);
                #pragma unroll
                for (int d4 = 0; d4 < 8; ++d4) {
                    float4 kr = *reinterpret_cast<float4*>(&ks[j * SD + d4 * 4]);
                    s4.x += qr[d4].x * kr.x; s4.y += qr[d4].y * kr.y;
                    s4.z += qr[d4].z * kr.z; s4.w += qr[d4].w * kr.w;
                }
                float dot = (s4.x + s4.y) + (s4.z + s4.w);
                int idx = ((iy - j / WS) + WS - 1) * (2 * WS - 1)
                        + ((ix - j % WS) + WS - 1);
                float b = g_cpb[idx * NH + h];
                float sig = 16.0f / (1.0f + __expf(-b));
                float m = (ri != rgn[j]) ? -100.0f : 0.0f;
                lg[i * LS + j] = dot + sig + m;
            }
        }
    }
    __syncthreads();

    // softmax: one warp per row, lanes cover j and j+32
    for (int i = warp; i < N; i += 4) {
        float a = (lane < N)      ? lg[i * LS + lane]      : -1e30f;
        float b = (lane + 32 < N) ? lg[i * LS + lane + 32] : -1e30f;
        float m = fmaxf(a, b);
        #pragma unroll
        for (int o = 16; o > 0; o >>= 1) m = fmaxf(m, __shfl_xor_sync(0xffffffffu, m, o));
        float e1 = (lane < N)      ? __expf(a - m) : 0.0f;
        float e2 = (lane + 32 < N) ? __expf(b - m) : 0.0f;
        float s = e1 + e2;
        #pragma unroll
        for (int o = 16; o > 0; o >>= 1) s += __shfl_xor_sync(0xffffffffu, s, o);
        float inv = 1.0f / s;
        if (lane < N)      lg[i * LS + lane]      = e1 * inv;
        if (lane + 32 < N) lg[i * LS + lane + 32] = e2 * inv;
    }
    __syncthreads();

    // out = attn @ v -> g_win (window layout, head-interleaved), float4 stores
    float* dst = g_win + (size_t)bw * N * C + h * HD;
    for (int e = tid; e < N * 8; e += 128) {
        int i = e >> 3, d4 = (e & 7) * 4;
        float4 acc = make_float4(0.f, 0.f, 0.f, 0.f);
        const float* li = &lg[i * LS];
        #pragma unroll 7
        for (int j = 0; j < N; ++j) {
            float w = li[j];
            float4 v = *reinterpret_cast<float4*>(&vs[j * SD + d4]);
            acc.x += w * v.x; acc.y += w * v.y; acc.z += w * v.z; acc.w += w * v.w;
        }
        *reinterpret_cast<float4*>(&dst[(size_t)i * C + d4]) = acc;
    }
}

// ---------------- block-wide sum over 192 threads ---------------------------
__device__ __forceinline__ float block_sum192(float v, float* red) {
    #pragma unroll
    for (int o = 16; o > 0; o >>= 1) v += __shfl_down_sync(0xffffffffu, v, o);
    int wid = threadIdx.x >> 5;
    if ((threadIdx.x & 31) == 0) red[wid] = v;
    __syncthreads();
    float s = red[0] + red[1] + red[2] + red[3] + red[4] + red[5];
    __syncthreads();
    return s;
}

// hidden[dst] = x[dst] + LN1(proj[t]), with window-reverse + un-shift scatter
__global__ __launch_bounds__(192)
void postattn_kernel(const float* __restrict__ x,
                     const float* __restrict__ g1, const float* __restrict__ b1) {
    __shared__ float red[6];
    int t = blockIdx.x, c = threadIdx.x;
    int bw = t / N, n = t % N;
    int b  = bw / NW, w_ = bw % NW;
    int wy = w_ / WG, wx = w_ % WG;
    int hh = wy * WS + n / WS, ww = wx * WS + n % WS;
    int oh = (hh + SS) % Hh, ow = (ww + SS) % Ww;
    size_t dst = ((size_t)(b * Hh + oh) * Ww + ow) * C;

    float v = g_q[(size_t)t * C + c];          // proj output row
    float mean = block_sum192(v, red) * (1.0f / C);
    float dv = v - mean;
    float var = block_sum192(dv * dv, red) * (1.0f / C);
    float ln = dv * rsqrtf(var + EPS) * g1[c] + b1[c];
    g_k[dst + c] = x[dst + c] + ln;            // hidden (natural layout)
}

// out[t] = hidden[t] + LN2(mlp[t])
__global__ __launch_bounds__(192)
void final_kernel(const float* __restrict__ g2, const float* __restrict__ b2,
                  float* __restrict__ out) {
    __shared__ float red[6];
    int t = blockIdx.x, c = threadIdx.x;
    float v = g_v[(size_t)t * C + c];          // mlp output row
    float mean = block_sum192(v, red) * (1.0f / C);
    float dv = v - mean;
    float var = block_sum192(dv * dv, red) * (1.0f / C);
    float ln = dv * rsqrtf(var + EPS) * g2[c] + b2[c];
    out[(size_t)t * C + c] = g_k[(size_t)t * C + c] + ln;
}

} // namespace

// ============================================================================
extern "C" void kernel_launch(void* const* d_in, const int* in_sizes, int n_in,
                              void* d_out, int out_size) {
    const float* x      = (const float*)d_in[0];
    const float* ln1_g  = (const float*)d_in[1];
    const float* ln1_b  = (const float*)d_in[2];
    const float* ln2_g  = (const float*)d_in[3];
    const float* ln2_b  = (const float*)d_in[4];
    const float* q_w    = (const float*)d_in[5];
    const float* q_b    = (const float*)d_in[6];
    const float* k_w    = (const float*)d_in[7];
    const float* v_w    = (const float*)d_in[8];
    const float* v_b    = (const float*)d_in[9];
    const float* p_w    = (const float*)d_in[10];
    const float* p_b    = (const float*)d_in[11];
    const float* lscale = (const float*)d_in[12];
    const float* cpb_w0 = (const float*)d_in[13];
    const float* cpb_b0 = (const float*)d_in[14];
    const float* cpb_w1 = (const float*)d_in[15];
    const float* fc1_w  = (const float*)d_in[16];
    const float* fc1_b  = (const float*)d_in[17];
    const float* fc2_w  = (const float*)d_in[18];
    const float* fc2_b  = (const float*)d_in[19];
    float* out = (float*)d_out;

    float *p_qkv, *p_win, *p_q, *p_k, *p_v, *p_m1, *p_wqkv, *p_bqkv;
    cudaGetSymbolAddress((void**)&p_qkv,  g_qkv);
    cudaGetSymbolAddress((void**)&p_win,  g_win);
    cudaGetSymbolAddress((void**)&p_q,    g_q);
    cudaGetSymbolAddress((void**)&p_k,    g_k);
    cudaGetSymbolAddress((void**)&p_v,    g_v);
    cudaGetSymbolAddress((void**)&p_m1,   g_mlp1);
    cudaGetSymbolAddress((void**)&p_wqkv, g_wqkv);
    cudaGetSymbolAddress((void**)&p_bqkv, g_bqkv);

    // 1) CPB bias table + head scales; pack QKV weights
    cpb_kernel<<<169, 256>>>(cpb_w0, cpb_b0, cpb_w1, lscale);
    packqkv_kernel<<<C, QKVC>>>(q_w, k_w, v_w, q_b, v_b);

    // 2) fused shift+window-gather + QKV GEMM  (A = x with permuted rows)
    dim3 gQKV(QKVC / GBN, T / GBM);
    tf32gemm_kernel<<<gQKV, 128>>>(x, p_wqkv, p_bqkv, p_qkv, T, QKVC, C, 0, 1);

    // 3) fused attention (writes attn output into g_win)
    attn_kernel<<<BW * NH, 128>>>();

    // 4) output projection
    dim3 gC(C / GBN, T / GBM);
    tf32gemm_kernel<<<gC, 128>>>(p_win, p_w, p_b, p_q, T, C, C, 0, 0);

    // 5) window reverse + un-shift + LN1 + residual -> hidden (g_k)
    postattn_kernel<<<T, C>>>(x, ln1_g, ln1_b);

    // 6) fc1 + GELU
    dim3 gF1(C4 / GBN, T / GBM);
    tf32gemm_kernel<<<gF1, 128>>>(p_k, fc1_w, fc1_b, p_m1, T, C4, C, 1, 0);

    // 7) fc2
    tf32gemm_kernel<<<gC, 128>>>(p_m1, fc2_w, fc2_b, p_v, T, C, C4, 0, 0);

    // 8) hidden + LN2(mlp) -> out
    final_kernel<<<T, C>>>(ln2_g, ln2_b, out);
}

// round 8
// speedup vs baseline: 3.1299x; 1.3149x over previous
#include <cuda_runtime.h>
#include <cuda_fp16.h>
#include <math.h>
#include <stdint.h>

namespace {

constexpr int Bb  = 8;
constexpr int Hh  = 112;
constexpr int Ww  = 112;
constexpr int C   = 192;
constexpr int NH  = 6;
constexpr int HD  = 32;      // C / NH
constexpr int WS  = 7;
constexpr int SS  = 3;
constexpr int N   = 49;      // WS*WS
constexpr int WG  = Hh / WS; // 16
constexpr int NW  = WG * WG; // 256
constexpr int BW  = Bb * NW; // 2048
constexpr int T   = BW * N;  // 100352 tokens
constexpr int C4  = 4 * C;   // 768
constexpr int QKVC = 3 * C;  // 576
constexpr float EPS    = 1e-5f;
constexpr float LOG100 = 4.605170185988091f;

// ---------------- scratch (static device globals; no allocation) -----------
__device__ float g_qkv [(size_t)T * QKVC]; // fused q|k|v (window-token layout)
__device__ float g_win [(size_t)T * C];    // attn output (window layout)
__device__ float g_q   [(size_t)T * C];    // proj output
__device__ float g_k   [(size_t)T * C];    // hidden (natural layout)
__device__ float g_v   [(size_t)T * C];    // mlp output
__device__ float g_mlp1[(size_t)T * C4];   // fc1 output
__device__ __half g_wqkvT[QKVC * C];       // packed qkv weight, transposed [576][192], half
__device__ __half g_pwT  [C * C];          // proj weight transposed [192][192]
__device__ __half g_fc1T [C4 * C];         // fc1 weight transposed [768][192]
__device__ __half g_fc2T [C * C4];         // fc2 weight transposed [192][768]
__device__ float g_bqkv[QKVC];             // packed qkv bias
__device__ float g_cpb [169 * NH];         // CPB MLP output table (169 x NH)
__device__ float g_scl [NH];               // per-head logit scale

// ---------------- CPB bias table MLP: (169,2)->512(relu)->NH ---------------
__global__ void cpb_kernel(const float* __restrict__ w0, const float* __restrict__ b0,
                           const float* __restrict__ w1, const float* __restrict__ ls) {
    int r   = blockIdx.x;     // 0..168
    int tid = threadIdx.x;    // 256 threads
    __shared__ float part[256][NH];

    int ri = r / 13, rj = r % 13;
    float t0 = (ri - 6) * (8.0f / 6.0f);
    float t1 = (rj - 6) * (8.0f / 6.0f);
    float v0 = copysignf(log2f(fabsf(t0) + 1.0f) * (1.0f / 3.0f), t0);
    float v1 = copysignf(log2f(fabsf(t1) + 1.0f) * (1.0f / 3.0f), t1);

    float acc[NH];
    #pragma unroll
    for (int h = 0; h < NH; ++h) acc[h] = 0.0f;
    for (int j = tid; j < 512; j += 256) {
        float hv = fmaxf(v0 * w0[j] + v1 * w0[512 + j] + b0[j], 0.0f);
        #pragma unroll
        for (int h = 0; h < NH; ++h) acc[h] += hv * w1[j * NH + h];
    }
    #pragma unroll
    for (int h = 0; h < NH; ++h) part[tid][h] = acc[h];
    __syncthreads();
    if (tid < NH) {
        float s = 0.0f;
        for (int i = 0; i < 256; ++i) s += part[i][tid];
        g_cpb[r * NH + tid] = s;
        if (r == 0) g_scl[tid] = expf(fminf(ls[tid], LOG100));
    }
}

// ---------------- weight packing: transpose to half [Nn][K] ----------------
__global__ void packT_kernel(const float* __restrict__ W, __half* __restrict__ WT,
                             int K, int Nn) {
    int n = blockIdx.x;           // 0..Nn-1
    for (int k = threadIdx.x; k < K; k += blockDim.x)
        WT[(size_t)n * K + k] = __float2half(W[(size_t)k * Nn + n]);
}

// qkv: j in [0,576) selects q/k/v column; output row j = weight column j over K=C
__global__ void packqkvT_kernel(const float* __restrict__ qw, const float* __restrict__ kw,
                                const float* __restrict__ vw, const float* __restrict__ qb,
                                const float* __restrict__ vb) {
    int j = blockIdx.x;           // 0..575
    const float* src; int jj;
    if (j < C)            { src = qw; jj = j; }
    else if (j < 2 * C)   { src = kw; jj = j - C; }
    else                  { src = vw; jj = j - 2 * C; }
    for (int k = threadIdx.x; k < C; k += blockDim.x)
        g_wqkvT[(size_t)j * C + k] = __float2half(src[(size_t)k * C + jj]);
    if (threadIdx.x == 0) {
        float b;
        if (j < C)          b = qb[j];
        else if (j < 2 * C) b = 0.0f;
        else                b = vb[j - 2 * C];
        g_bqkv[j] = b;
    }
}

// ---------------- fp16 tensor-core GEMM: C = act(A@B + bias) ---------------
// A: MxK row-major fp32 (optionally row-gathered). BT: half, [Nn][K] row-major
// (i.e. B col-major). M%128==0, Nn%64==0, K%16==0.
// 4 warps, warp tile 64x32, mma.m16n8k16.f16, ping-pong smem, 1 sync/K-tile.
constexpr int GBM = 128, GBN = 64, GBK = 16;
constexpr int AST = 24;   // half stride per A row (16 + 8 pad)
constexpr int BST = 24;   // half stride per B col

__device__ __forceinline__ float gelu_tanh(float v) {
    return 0.5f * v * (1.0f + tanhf(0.7978845608028654f * (v + 0.044715f * v * v * v)));
}

__device__ __forceinline__ void mma_f16(float* d, const uint32_t* a, const uint32_t* b) {
    asm volatile(
        "mma.sync.aligned.m16n8k16.row.col.f32.f16.f16.f32 "
        "{%0,%1,%2,%3},{%4,%5,%6,%7},{%8,%9},{%0,%1,%2,%3};"
        : "+f"(d[0]), "+f"(d[1]), "+f"(d[2]), "+f"(d[3])
        : "r"(a[0]), "r"(a[1]), "r"(a[2]), "r"(a[3]), "r"(b[0]), "r"(b[1]));
}

__device__ __forceinline__ uint32_t pack_half2(float x, float y) {
    __half2 h = __floats2half2_rn(x, y);
    return *reinterpret_cast<uint32_t*>(&h);
}

__global__ __launch_bounds__(128)
void h16gemm_kernel(const float* __restrict__ A, const __half* __restrict__ BT,
                    const float* __restrict__ bias, float* __restrict__ Cmat,
                    int M, int Nn, int K, int act, int gatherA) {
    __shared__ __half As[2][GBM * AST];
    __shared__ __half Bs[2][GBN * BST];

    int tid  = threadIdx.x;            // 0..127
    int lane = tid & 31;
    int warp = tid >> 5;               // 0..3
    int gid  = lane >> 2;              // 0..7
    int tg   = lane & 3;               // 0..3
    int bm = blockIdx.y * GBM;
    int bn = blockIdx.x * GBN;
    int warp_m = (warp >> 1) * 64;     // 0 or 64
    int warp_n = (warp & 1) * 32;      // 0 or 32

    // A: 4 float4 per K-tile per thread
    const float* aSrc[4];
    int aRow[4], aK4[4];
    #pragma unroll
    for (int i = 0; i < 4; ++i) {
        int idx = tid + i * 128;        // float4 index within 128x16 tile
        int row = idx >> 2;
        aRow[i] = row;
        aK4[i]  = (idx & 3) * 4;
        int r = bm + row;
        size_t abase;
        if (gatherA) {
            int bw = r / N, n = r % N;
            int b  = bw / NW, w_ = bw % NW;
            int wy = w_ / WG, wx = w_ % WG;
            int hh = wy * WS + n / WS, ww = wx * WS + n % WS;
            int oh = (hh + SS) % Hh, ow = (ww + SS) % Ww;
            abase = ((size_t)(b * Hh + oh) * Ww + ow) * (size_t)K;
        } else {
            abase = (size_t)r * K;
        }
        aSrc[i] = A + abase + aK4[i];
    }
    // B: one uint4 (8 halves along K) per thread per K-tile
    int bCol = tid >> 1, bK8 = (tid & 1) * 8;
    const __half* bSrc = BT + (size_t)(bn + bCol) * K + bK8;

    float acc[4][4][4];
    #pragma unroll
    for (int mt = 0; mt < 4; ++mt)
        #pragma unroll
        for (int nt = 0; nt < 4; ++nt)
            #pragma unroll
            for (int e = 0; e < 4; ++e) acc[mt][nt][e] = 0.0f;

    float4 aReg[4];
    uint4  bReg;
    #pragma unroll
    for (int i = 0; i < 4; ++i)
        aReg[i] = *reinterpret_cast<const float4*>(aSrc[i]);
    bReg = *reinterpret_cast<const uint4*>(bSrc);

    int nTiles = K / GBK;
    for (int it = 0; it < nTiles; ++it) {
        int cur = it & 1;
        // stage current tile (A: cvt fp32->half2; B: raw copy)
        #pragma unroll
        for (int i = 0; i < 4; ++i) {
            uint2 u;
            u.x = pack_half2(aReg[i].x, aReg[i].y);
            u.y = pack_half2(aReg[i].z, aReg[i].w);
            *reinterpret_cast<uint2*>(&As[cur][aRow[i] * AST + aK4[i]]) = u;
        }
        *reinterpret_cast<uint4*>(&Bs[cur][bCol * BST + bK8]) = bReg;
        __syncthreads();

        // prefetch next tile (overlaps compute below)
        if (it + 1 < nTiles) {
            int off = (it + 1) * GBK;
            #pragma unroll
            for (int i = 0; i < 4; ++i)
                aReg[i] = *reinterpret_cast<const float4*>(aSrc[i] + off);
            bReg = *reinterpret_cast<const uint4*>(bSrc + off);
        }

        // one m16n8k16 step covers the whole BK=16 tile
        uint32_t af[4][4];
        #pragma unroll
        for (int mt = 0; mt < 4; ++mt) {
            int r0 = warp_m + mt * 16 + gid;
            af[mt][0] = *reinterpret_cast<uint32_t*>(&As[cur][ r0      * AST + tg * 2    ]);
            af[mt][1] = *reinterpret_cast<uint32_t*>(&As[cur][(r0 + 8) * AST + tg * 2    ]);
            af[mt][2] = *reinterpret_cast<uint32_t*>(&As[cur][ r0      * AST + tg * 2 + 8]);
            af[mt][3] = *reinterpret_cast<uint32_t*>(&As[cur][(r0 + 8) * AST + tg * 2 + 8]);
        }
        uint32_t bf[4][2];
        #pragma unroll
        for (int nt = 0; nt < 4; ++nt) {
            int c0 = warp_n + nt * 8 + gid;
            bf[nt][0] = *reinterpret_cast<uint32_t*>(&Bs[cur][c0 * BST + tg * 2    ]);
            bf[nt][1] = *reinterpret_cast<uint32_t*>(&Bs[cur][c0 * BST + tg * 2 + 8]);
        }
        #pragma unroll
        for (int mt = 0; mt < 4; ++mt)
            #pragma unroll
            for (int nt = 0; nt < 4; ++nt)
                mma_f16(acc[mt][nt], af[mt], bf[nt]);
        __syncthreads();
    }

    // epilogue: bias + optional GELU, float2 stores (col even)
    #pragma unroll
    for (int mt = 0; mt < 4; ++mt) {
        #pragma unroll
        for (int r2 = 0; r2 < 2; ++r2) {
            int row = bm + warp_m + mt * 16 + gid + r2 * 8;
            #pragma unroll
            for (int nt = 0; nt < 4; ++nt) {
                int col = bn + warp_n + nt * 8 + tg * 2;
                float v0 = acc[mt][nt][r2 * 2 + 0];
                float v1 = acc[mt][nt][r2 * 2 + 1];
                if (bias) { v0 += bias[col]; v1 += bias[col + 1]; }
                if (act == 1) { v0 = gelu_tanh(v0); v1 = gelu_tanh(v1); }
                *reinterpret_cast<float2*>(&Cmat[(size_t)row * Nn + col]) =
                    make_float2(v0, v1);
            }
        }
    }
}

// ---------------- fused per-(window,head) attention (v2) --------------------
constexpr int SD = HD + 4;   // 36 floats: padded row stride for q/k/v
constexpr int LS = 52;       // padded row stride for logits

__global__ __launch_bounds__(128)
void attn_kernel() {
    int blk = blockIdx.x;          // 0..BW*NH-1
    int bw  = blk / NH, h = blk % NH;
    int tid = threadIdx.x;
    int warp = tid >> 5, lane = tid & 31;

    __shared__ float qs[N * SD], ks[N * SD], vs[N * SD];
    __shared__ float lg[N * LS];
    __shared__ int   rgn[N];
    __shared__ float scale_s;

    if (tid == 0) scale_s = g_scl[h];
    if (tid < N) {
        int w_ = bw % NW, wy = w_ / WG, wx = w_ % WG;
        int gh = wy * WS + tid / WS, gw = wx * WS + tid % WS;
        int rh = gh < Hh - WS ? 0 : (gh < Hh - SS ? 1 : 2);
        int rw = gw < Ww - WS ? 0 : (gw < Ww - SS ? 1 : 2);
        rgn[tid] = rh * 3 + rw;
    }

    // load q,k,v rows as float4
    const float* src = g_qkv + (size_t)bw * N * QKVC + h * HD;
    for (int e = tid; e < N * 8; e += 128) {
        int n = e >> 3, d4 = (e & 7) * 4;
        const float* row = src + (size_t)n * QKVC + d4;
        *reinterpret_cast<float4*>(&qs[n * SD + d4]) =
            *reinterpret_cast<const float4*>(row);
        *reinterpret_cast<float4*>(&ks[n * SD + d4]) =
            *reinterpret_cast<const float4*>(row + C);
        *reinterpret_cast<float4*>(&vs[n * SD + d4]) =
            *reinterpret_cast<const float4*>(row + 2 * C);
    }
    __syncthreads();

    // cosine-normalize rows (q also absorbs the logit scale)
    if (tid < 2 * N) {
        float* arr = (tid < N) ? qs : ks;
        int r = (tid < N) ? tid : tid - N;
        float ssum = 0.0f;
        #pragma unroll
        for (int d4 = 0; d4 < 8; ++d4) {
            float4 u = *reinterpret_cast<float4*>(&arr[r * SD + d4 * 4]);
            ssum += u.x * u.x + u.y * u.y + u.z * u.z + u.w * u.w;
        }
        float inv = 1.0f / fmaxf(sqrtf(ssum), 1e-12f);
        if (tid < N) inv *= scale_s;
        #pragma unroll
        for (int d4 = 0; d4 < 8; ++d4) {
            float4 u = *reinterpret_cast<float4*>(&arr[r * SD + d4 * 4]);
            u.x *= inv; u.y *= inv; u.z *= inv; u.w *= inv;
            *reinterpret_cast<float4*>(&arr[r * SD + d4 * 4]) = u;
        }
    }
    __syncthreads();

    // logits + CPB bias + shift mask. 2 threads per row; q row in registers.
    {
        int i = tid >> 1, p = tid & 1;
        if (i < N) {
            float4 qr[8];
            #pragma unroll
            for (int d4 = 0; d4 < 8; ++d4)
                qr[d4] = *reinterpret_cast<float4*>(&qs[i * SD + d4 * 4]);
            int iy = i / WS, ix = i % WS, ri = rgn[i];
            for (int j = p; j < N; j += 2) {
                float4 s4 = make_float4(0.f, 0.f, 0.f, 0.f);
                #pragma unroll
                for (int d4 = 0; d4 < 8; ++d4) {
                    float4 kr = *reinterpret_cast<float4*>(&ks[j * SD + d4 * 4]);
                    s4.x += qr[d4].x * kr.x; s4.y += qr[d4].y * kr.y;
                    s4.z += qr[d4].z * kr.z; s4.w += qr[d4].w * kr.w;
                }
                float dot = (s4.x + s4.y) + (s4.z + s4.w);
                int idx = ((iy - j / WS) + WS - 1) * (2 * WS - 1)
                        + ((ix - j % WS) + WS - 1);
                float b = g_cpb[idx * NH + h];
                float sig = 16.0f / (1.0f + __expf(-b));
                float m = (ri != rgn[j]) ? -100.0f : 0.0f;
                lg[i * LS + j] = dot + sig + m;
            }
        }
    }
    __syncthreads();

    // softmax: one warp per row, lanes cover j and j+32
    for (int i = warp; i < N; i += 4) {
        float a = (lane < N)      ? lg[i * LS + lane]      : -1e30f;
        float b = (lane + 32 < N) ? lg[i * LS + lane + 32] : -1e30f;
        float m = fmaxf(a, b);
        #pragma unroll
        for (int o = 16; o > 0; o >>= 1) m = fmaxf(m, __shfl_xor_sync(0xffffffffu, m, o));
        float e1 = (lane < N)      ? __expf(a - m) : 0.0f;
        float e2 = (lane + 32 < N) ? __expf(b - m) : 0.0f;
        float s = e1 + e2;
        #pragma unroll
        for (int o = 16; o > 0; o >>= 1) s += __shfl_xor_sync(0xffffffffu, s, o);
        float inv = 1.0f / s;
        if (lane < N)      lg[i * LS + lane]      = e1 * inv;
        if (lane + 32 < N) lg[i * LS + lane + 32] = e2 * inv;
    }
    __syncthreads();

    // out = attn @ v -> g_win (window layout, head-interleaved), float4 stores
    float* dst = g_win + (size_t)bw * N * C + h * HD;
    for (int e = tid; e < N * 8; e += 128) {
        int i = e >> 3, d4 = (e & 7) * 4;
        float4 acc = make_float4(0.f, 0.f, 0.f, 0.f);
        const float* li = &lg[i * LS];
        #pragma unroll 7
        for (int j = 0; j < N; ++j) {
            float w = li[j];
            float4 v = *reinterpret_cast<float4*>(&vs[j * SD + d4]);
            acc.x += w * v.x; acc.y += w * v.y; acc.z += w * v.z; acc.w += w * v.w;
        }
        *reinterpret_cast<float4*>(&dst[(size_t)i * C + d4]) = acc;
    }
}

// ---------------- block-wide sum over 192 threads ---------------------------
__device__ __forceinline__ float block_sum192(float v, float* red) {
    #pragma unroll
    for (int o = 16; o > 0; o >>= 1) v += __shfl_down_sync(0xffffffffu, v, o);
    int wid = threadIdx.x >> 5;
    if ((threadIdx.x & 31) == 0) red[wid] = v;
    __syncthreads();
    float s = red[0] + red[1] + red[2] + red[3] + red[4] + red[5];
    __syncthreads();
    return s;
}

// hidden[dst] = x[dst] + LN1(proj[t]), with window-reverse + un-shift scatter
__global__ __launch_bounds__(192)
void postattn_kernel(const float* __restrict__ x,
                     const float* __restrict__ g1, const float* __restrict__ b1) {
    __shared__ float red[6];
    int t = blockIdx.x, c = threadIdx.x;
    int bw = t / N, n = t % N;
    int b  = bw / NW, w_ = bw % NW;
    int wy = w_ / WG, wx = w_ % WG;
    int hh = wy * WS + n / WS, ww = wx * WS + n % WS;
    int oh = (hh + SS) % Hh, ow = (ww + SS) % Ww;
    size_t dst = ((size_t)(b * Hh + oh) * Ww + ow) * C;

    float v = g_q[(size_t)t * C + c];          // proj output row
    float mean = block_sum192(v, red) * (1.0f / C);
    float dv = v - mean;
    float var = block_sum192(dv * dv, red) * (1.0f / C);
    float ln = dv * rsqrtf(var + EPS) * g1[c] + b1[c];
    g_k[dst + c] = x[dst + c] + ln;            // hidden (natural layout)
}

// out[t] = hidden[t] + LN2(mlp[t])
__global__ __launch_bounds__(192)
void final_kernel(const float* __restrict__ g2, const float* __restrict__ b2,
                  float* __restrict__ out) {
    __shared__ float red[6];
    int t = blockIdx.x, c = threadIdx.x;
    float v = g_v[(size_t)t * C + c];          // mlp output row
    float mean = block_sum192(v, red) * (1.0f / C);
    float dv = v - mean;
    float var = block_sum192(dv * dv, red) * (1.0f / C);
    float ln = dv * rsqrtf(var + EPS) * g2[c] + b2[c];
    out[(size_t)t * C + c] = g_k[(size_t)t * C + c] + ln;
}

} // namespace

// ============================================================================
extern "C" void kernel_launch(void* const* d_in, const int* in_sizes, int n_in,
                              void* d_out, int out_size) {
    const float* x      = (const float*)d_in[0];
    const float* ln1_g  = (const float*)d_in[1];
    const float* ln1_b  = (const float*)d_in[2];
    const float* ln2_g  = (const float*)d_in[3];
    const float* ln2_b  = (const float*)d_in[4];
    const float* q_w    = (const float*)d_in[5];
    const float* q_b    = (const float*)d_in[6];
    const float* k_w    = (const float*)d_in[7];
    const float* v_w    = (const float*)d_in[8];
    const float* v_b    = (const float*)d_in[9];
    const float* p_w    = (const float*)d_in[10];
    const float* p_b    = (const float*)d_in[11];
    const float* lscale = (const float*)d_in[12];
    const float* cpb_w0 = (const float*)d_in[13];
    const float* cpb_b0 = (const float*)d_in[14];
    const float* cpb_w1 = (const float*)d_in[15];
    const float* fc1_w  = (const float*)d_in[16];
    const float* fc1_b  = (const float*)d_in[17];
    const float* fc2_w  = (const float*)d_in[18];
    const float* fc2_b  = (const float*)d_in[19];
    float* out = (float*)d_out;

    float *p_qkv, *p_win, *p_q, *p_k, *p_v, *p_m1, *p_bqkv;
    __half *p_wqkvT, *p_pwT, *p_fc1T, *p_fc2T;
    cudaGetSymbolAddress((void**)&p_qkv,   g_qkv);
    cudaGetSymbolAddress((void**)&p_win,   g_win);
    cudaGetSymbolAddress((void**)&p_q,     g_q);
    cudaGetSymbolAddress((void**)&p_k,     g_k);
    cudaGetSymbolAddress((void**)&p_v,     g_v);
    cudaGetSymbolAddress((void**)&p_m1,    g_mlp1);
    cudaGetSymbolAddress((void**)&p_bqkv,  g_bqkv);
    cudaGetSymbolAddress((void**)&p_wqkvT, g_wqkvT);
    cudaGetSymbolAddress((void**)&p_pwT,   g_pwT);
    cudaGetSymbolAddress((void**)&p_fc1T,  g_fc1T);
    cudaGetSymbolAddress((void**)&p_fc2T,  g_fc2T);

    // 1) CPB bias table + head scales; pack/transpose weights to half
    cpb_kernel<<<169, 256>>>(cpb_w0, cpb_b0, cpb_w1, lscale);
    packqkvT_kernel<<<QKVC, 192>>>(q_w, k_w, v_w, q_b, v_b);
    packT_kernel<<<C,  192>>>(p_w,   p_pwT,  C,  C);
    packT_kernel<<<C4, 192>>>(fc1_w, p_fc1T, C,  C4);
    packT_kernel<<<C,  192>>>(fc2_w, p_fc2T, C4, C);

    // 2) fused shift+window-gather + QKV GEMM  (A = x with permuted rows)
    dim3 gQKV(QKVC / GBN, T / GBM);
    h16gemm_kernel<<<gQKV, 128>>>(x, p_wqkvT, p_bqkv, p_qkv, T, QKVC, C, 0, 1);

    // 3) fused attention (writes attn output into g_win)
    attn_kernel<<<BW * NH, 128>>>();

    // 4) output projection
    dim3 gC(C / GBN, T / GBM);
    h16gemm_kernel<<<gC, 128>>>(p_win, p_pwT, p_b, p_q, T, C, C, 0, 0);

    // 5) window reverse + un-shift + LN1 + residual -> hidden (g_k)
    postattn_kernel<<<T, C>>>(x, ln1_g, ln1_b);

    // 6) fc1 + GELU
    dim3 gF1(C4 / GBN, T / GBM);
    h16gemm_kernel<<<gF1, 128>>>(p_k, p_fc1T, fc1_b, p_m1, T, C4, C, 1, 0);

    // 7) fc2
    h16gemm_kernel<<<gC, 128>>>(p_m1, p_fc2T, fc2_b, p_v, T, C, C4, 0, 0);

    // 8) hidden + LN2(mlp) -> out
    final_kernel<<<T, C>>>(ln2_g, ln2_b, out);
}

// round 9
// speedup vs baseline: 3.5991x; 1.1499x over previous
#include <cuda_runtime.h>
#include <cuda_fp16.h>
#include <math.h>
#include <stdint.h>

namespace {

constexpr int Bb  = 8;
constexpr int Hh  = 112;
constexpr int Ww  = 112;
constexpr int C   = 192;
constexpr int NH  = 6;
constexpr int HD  = 32;      // C / NH
constexpr int WS  = 7;
constexpr int SS  = 3;
constexpr int N   = 49;      // WS*WS
constexpr int WG  = Hh / WS; // 16
constexpr int NW  = WG * WG; // 256
constexpr int BW  = Bb * NW; // 2048
constexpr int T   = BW * N;  // 100352 tokens
constexpr int C4  = 4 * C;   // 768
constexpr int QKVC = 3 * C;  // 576
constexpr float EPS    = 1e-5f;
constexpr float LOG100 = 4.605170185988091f;

// ---------------- scratch (static device globals; no allocation) -----------
__device__ float g_qkv [(size_t)T * QKVC]; // fused q|k|v (window-token layout)
__device__ float g_win [(size_t)T * C];    // attn output (window layout)
__device__ float g_q   [(size_t)T * C];    // proj output
__device__ float g_k   [(size_t)T * C];    // hidden (natural layout)
__device__ float g_v   [(size_t)T * C];    // mlp output
__device__ float g_mlp1[(size_t)T * C4];   // fc1 output
__device__ __half g_wqkvT[QKVC * C];       // packed qkv weight, transposed, half
__device__ __half g_pwT  [C * C];          // proj weight transposed
__device__ __half g_fc1T [C4 * C];         // fc1 weight transposed
__device__ __half g_fc2T [C * C4];         // fc2 weight transposed
__device__ float g_bqkv[QKVC];             // packed qkv bias
__device__ float g_cpb [169 * NH];         // 16*sigmoid(CPB bias) table (169 x NH)
__device__ float g_scl [NH];               // per-head logit scale

// ---------------- CPB bias table MLP: (169,2)->512(relu)->NH ---------------
// NOTE: stores 16*sigmoid(bias) directly (what attention adds to logits).
__global__ void cpb_kernel(const float* __restrict__ w0, const float* __restrict__ b0,
                           const float* __restrict__ w1, const float* __restrict__ ls) {
    int r   = blockIdx.x;     // 0..168
    int tid = threadIdx.x;    // 256 threads
    __shared__ float part[256][NH];

    int ri = r / 13, rj = r % 13;
    float t0 = (ri - 6) * (8.0f / 6.0f);
    float t1 = (rj - 6) * (8.0f / 6.0f);
    float v0 = copysignf(log2f(fabsf(t0) + 1.0f) * (1.0f / 3.0f), t0);
    float v1 = copysignf(log2f(fabsf(t1) + 1.0f) * (1.0f / 3.0f), t1);

    float acc[NH];
    #pragma unroll
    for (int h = 0; h < NH; ++h) acc[h] = 0.0f;
    for (int j = tid; j < 512; j += 256) {
        float hv = fmaxf(v0 * w0[j] + v1 * w0[512 + j] + b0[j], 0.0f);
        #pragma unroll
        for (int h = 0; h < NH; ++h) acc[h] += hv * w1[j * NH + h];
    }
    #pragma unroll
    for (int h = 0; h < NH; ++h) part[tid][h] = acc[h];
    __syncthreads();
    if (tid < NH) {
        float s = 0.0f;
        for (int i = 0; i < 256; ++i) s += part[i][tid];
        g_cpb[r * NH + tid] = 16.0f / (1.0f + expf(-s));
        if (r == 0) g_scl[tid] = expf(fminf(ls[tid], LOG100));
    }
}

// ---------------- weight packing: transpose to half [Nn][K] ----------------
__global__ void packT_kernel(const float* __restrict__ W, __half* __restrict__ WT,
                             int K, int Nn) {
    int n = blockIdx.x;           // 0..Nn-1
    for (int k = threadIdx.x; k < K; k += blockDim.x)
        WT[(size_t)n * K + k] = __float2half(W[(size_t)k * Nn + n]);
}

__global__ void packqkvT_kernel(const float* __restrict__ qw, const float* __restrict__ kw,
                                const float* __restrict__ vw, const float* __restrict__ qb,
                                const float* __restrict__ vb) {
    int j = blockIdx.x;           // 0..575
    const float* src; int jj;
    if (j < C)            { src = qw; jj = j; }
    else if (j < 2 * C)   { src = kw; jj = j - C; }
    else                  { src = vw; jj = j - 2 * C; }
    for (int k = threadIdx.x; k < C; k += blockDim.x)
        g_wqkvT[(size_t)j * C + k] = __float2half(src[(size_t)k * C + jj]);
    if (threadIdx.x == 0) {
        float b;
        if (j < C)          b = qb[j];
        else if (j < 2 * C) b = 0.0f;
        else                b = vb[j - 2 * C];
        g_bqkv[j] = b;
    }
}

// ---------------- fp16 tensor-core GEMM: C = act(A@B + bias) ---------------
constexpr int GBM = 128, GBN = 64, GBK = 16;
constexpr int AST = 24;   // half stride per A row (16 + 8 pad)
constexpr int BST = 24;   // half stride per B col

__device__ __forceinline__ float gelu_tanh(float v) {
    return 0.5f * v * (1.0f + tanhf(0.7978845608028654f * (v + 0.044715f * v * v * v)));
}

__device__ __forceinline__ void mma_f16(float* d, const uint32_t* a, const uint32_t* b) {
    asm volatile(
        "mma.sync.aligned.m16n8k16.row.col.f32.f16.f16.f32 "
        "{%0,%1,%2,%3},{%4,%5,%6,%7},{%8,%9},{%0,%1,%2,%3};"
        : "+f"(d[0]), "+f"(d[1]), "+f"(d[2]), "+f"(d[3])
        : "r"(a[0]), "r"(a[1]), "r"(a[2]), "r"(a[3]), "r"(b[0]), "r"(b[1]));
}

__device__ __forceinline__ uint32_t pack_half2(float x, float y) {
    __half2 h = __floats2half2_rn(x, y);
    return *reinterpret_cast<uint32_t*>(&h);
}

__global__ __launch_bounds__(128)
void h16gemm_kernel(const float* __restrict__ A, const __half* __restrict__ BT,
                    const float* __restrict__ bias, float* __restrict__ Cmat,
                    int M, int Nn, int K, int act, int gatherA) {
    __shared__ __half As[2][GBM * AST];
    __shared__ __half Bs[2][GBN * BST];

    int tid  = threadIdx.x;            // 0..127
    int lane = tid & 31;
    int warp = tid >> 5;               // 0..3
    int gid  = lane >> 2;              // 0..7
    int tg   = lane & 3;               // 0..3
    int bm = blockIdx.y * GBM;
    int bn = blockIdx.x * GBN;
    int warp_m = (warp >> 1) * 64;     // 0 or 64
    int warp_n = (warp & 1) * 32;      // 0 or 32

    const float* aSrc[4];
    int aRow[4], aK4[4];
    #pragma unroll
    for (int i = 0; i < 4; ++i) {
        int idx = tid + i * 128;        // float4 index within 128x16 tile
        int row = idx >> 2;
        aRow[i] = row;
        aK4[i]  = (idx & 3) * 4;
        int r = bm + row;
        size_t abase;
        if (gatherA) {
            int bw = r / N, n = r % N;
            int b  = bw / NW, w_ = bw % NW;
            int wy = w_ / WG, wx = w_ % WG;
            int hh = wy * WS + n / WS, ww = wx * WS + n % WS;
            int oh = (hh + SS) % Hh, ow = (ww + SS) % Ww;
            abase = ((size_t)(b * Hh + oh) * Ww + ow) * (size_t)K;
        } else {
            abase = (size_t)r * K;
        }
        aSrc[i] = A + abase + aK4[i];
    }
    int bCol = tid >> 1, bK8 = (tid & 1) * 8;
    const __half* bSrc = BT + (size_t)(bn + bCol) * K + bK8;

    float acc[4][4][4];
    #pragma unroll
    for (int mt = 0; mt < 4; ++mt)
        #pragma unroll
        for (int nt = 0; nt < 4; ++nt)
            #pragma unroll
            for (int e = 0; e < 4; ++e) acc[mt][nt][e] = 0.0f;

    float4 aReg[4];
    uint4  bReg;
    #pragma unroll
    for (int i = 0; i < 4; ++i)
        aReg[i] = *reinterpret_cast<const float4*>(aSrc[i]);
    bReg = *reinterpret_cast<const uint4*>(bSrc);

    int nTiles = K / GBK;
    for (int it = 0; it < nTiles; ++it) {
        int cur = it & 1;
        #pragma unroll
        for (int i = 0; i < 4; ++i) {
            uint2 u;
            u.x = pack_half2(aReg[i].x, aReg[i].y);
            u.y = pack_half2(aReg[i].z, aReg[i].w);
            *reinterpret_cast<uint2*>(&As[cur][aRow[i] * AST + aK4[i]]) = u;
        }
        *reinterpret_cast<uint4*>(&Bs[cur][bCol * BST + bK8]) = bReg;
        __syncthreads();

        if (it + 1 < nTiles) {
            int off = (it + 1) * GBK;
            #pragma unroll
            for (int i = 0; i < 4; ++i)
                aReg[i] = *reinterpret_cast<const float4*>(aSrc[i] + off);
            bReg = *reinterpret_cast<const uint4*>(bSrc + off);
        }

        uint32_t af[4][4];
        #pragma unroll
        for (int mt = 0; mt < 4; ++mt) {
            int r0 = warp_m + mt * 16 + gid;
            af[mt][0] = *reinterpret_cast<uint32_t*>(&As[cur][ r0      * AST + tg * 2    ]);
            af[mt][1] = *reinterpret_cast<uint32_t*>(&As[cur][(r0 + 8) * AST + tg * 2    ]);
            af[mt][2] = *reinterpret_cast<uint32_t*>(&As[cur][ r0      * AST + tg * 2 + 8]);
            af[mt][3] = *reinterpret_cast<uint32_t*>(&As[cur][(r0 + 8) * AST + tg * 2 + 8]);
        }
        uint32_t bf[4][2];
        #pragma unroll
        for (int nt = 0; nt < 4; ++nt) {
            int c0 = warp_n + nt * 8 + gid;
            bf[nt][0] = *reinterpret_cast<uint32_t*>(&Bs[cur][c0 * BST + tg * 2    ]);
            bf[nt][1] = *reinterpret_cast<uint32_t*>(&Bs[cur][c0 * BST + tg * 2 + 8]);
        }
        #pragma unroll
        for (int mt = 0; mt < 4; ++mt)
            #pragma unroll
            for (int nt = 0; nt < 4; ++nt)
                mma_f16(acc[mt][nt], af[mt], bf[nt]);
        __syncthreads();
    }

    #pragma unroll
    for (int mt = 0; mt < 4; ++mt) {
        #pragma unroll
        for (int r2 = 0; r2 < 2; ++r2) {
            int row = bm + warp_m + mt * 16 + gid + r2 * 8;
            #pragma unroll
            for (int nt = 0; nt < 4; ++nt) {
                int col = bn + warp_n + nt * 8 + tg * 2;
                float v0 = acc[mt][nt][r2 * 2 + 0];
                float v1 = acc[mt][nt][r2 * 2 + 1];
                if (bias) { v0 += bias[col]; v1 += bias[col + 1]; }
                if (act == 1) { v0 = gelu_tanh(v0); v1 = gelu_tanh(v1); }
                *reinterpret_cast<float2*>(&Cmat[(size_t)row * Nn + col]) =
                    make_float2(v0, v1);
            }
        }
    }
}

// ---------------- fused per-(window,head) attention (v3: tensor cores) -----
// One block per (window, head), 128 threads = 4 warps. Warp w owns M-rows
// [16w,16w+16). QK^T and P@V via mma.m16n8k16; softmax in registers.
// qh/kh: half [64][40] (rows=tokens, cols=dims). vT: half [32][72]
// (rows=dims, cols=tokens). All padding zeroed.
constexpr int QKS = 40;   // half stride of qh/kh rows (20 uint32)
constexpr int VTS = 72;   // half stride of vT rows (36 uint32)

__global__ __launch_bounds__(128)
void attn_kernel() {
    int blk = blockIdx.x;          // 0..BW*NH-1
    int bw  = blk / NH, h = blk % NH;
    int tid = threadIdx.x;
    int warp = tid >> 5, lane = tid & 31;
    int gid  = lane >> 2, tg = lane & 3;

    __shared__ __half qh[64 * QKS];
    __shared__ __half kh[64 * QKS];
    __shared__ __half vT[32 * VTS];
    __shared__ float cpb_s[169];
    __shared__ int   joff_s[64];
    __shared__ int   rgn_s[64];
    __shared__ float scale_s;

    uint32_t* qh32 = reinterpret_cast<uint32_t*>(qh);
    uint32_t* kh32 = reinterpret_cast<uint32_t*>(kh);
    uint32_t* vT32 = reinterpret_cast<uint32_t*>(vT);

    // zero the half buffers (covers all padding)
    for (int i = tid; i < 64 * QKS / 2; i += 128) { qh32[i] = 0u; kh32[i] = 0u; }
    for (int i = tid; i < 32 * VTS / 2; i += 128) vT32[i] = 0u;

    if (tid == 0) scale_s = g_scl[h];
    for (int r = tid; r < 169; r += 128) cpb_s[r] = g_cpb[r * NH + h];
    if (tid < 64) {
        int j = tid;
        if (j < N) {
            int jy = j / WS, jx = j % WS;
            joff_s[j] = (6 - jy) * 13 + (6 - jx);
            int w_ = bw % NW, wy = w_ / WG, wx = w_ % WG;
            int gh = wy * WS + jy, gw = wx * WS + jx;
            int rh = gh < Hh - WS ? 0 : (gh < Hh - SS ? 1 : 2);
            int rw = gw < Ww - WS ? 0 : (gw < Ww - SS ? 1 : 2);
            rgn_s[j] = rh * 3 + rw;
        } else { joff_s[j] = 0; rgn_s[j] = -1; }
    }
    __syncthreads();

    // normalize q/k rows (fp32) and store as half
    if (tid < 2 * N) {
        int isK = tid >= N;
        int r = isK ? tid - N : tid;
        const float* row = g_qkv + (size_t)(bw * N + r) * QKVC + h * HD + (isK ? C : 0);
        float4 u[8];
        float ssum = 0.0f;
        #pragma unroll
        for (int d4 = 0; d4 < 8; ++d4) {
            u[d4] = *reinterpret_cast<const float4*>(row + d4 * 4);
            ssum += u[d4].x * u[d4].x + u[d4].y * u[d4].y
                  + u[d4].z * u[d4].z + u[d4].w * u[d4].w;
        }
        float inv = 1.0f / fmaxf(sqrtf(ssum), 1e-12f);
        if (!isK) inv *= scale_s;
        uint32_t* dst = (isK ? kh32 : qh32) + r * (QKS / 2);
        #pragma unroll
        for (int d4 = 0; d4 < 8; ++d4) {
            dst[d4 * 2 + 0] = pack_half2(u[d4].x * inv, u[d4].y * inv);
            dst[d4 * 2 + 1] = pack_half2(u[d4].z * inv, u[d4].w * inv);
        }
    }
    // v transposed into vT[dim][token]
    for (int e = tid; e < N * HD; e += 128) {
        int tok = e >> 5, d = e & 31;
        float v = g_qkv[(size_t)(bw * N + tok) * QKVC + 2 * C + h * HD + d];
        vT[d * VTS + tok] = __float2half(v);
    }
    __syncthreads();

    int m0 = warp * 16;
    int r0 = m0 + gid, r1 = r0 + 8;

    // ---- S = Q @ K^T  (16 x 64 per warp) ----
    float sacc[8][4];
    #pragma unroll
    for (int nt = 0; nt < 8; ++nt)
        #pragma unroll
        for (int e = 0; e < 4; ++e) sacc[nt][e] = 0.0f;

    #pragma unroll
    for (int ks = 0; ks < 2; ++ks) {
        uint32_t a[4];
        a[0] = qh32[ r0       * (QKS / 2) + ks * 8 + tg    ];
        a[1] = qh32[ r1       * (QKS / 2) + ks * 8 + tg    ];
        a[2] = qh32[ r0       * (QKS / 2) + ks * 8 + tg + 4];
        a[3] = qh32[ r1       * (QKS / 2) + ks * 8 + tg + 4];
        #pragma unroll
        for (int nt = 0; nt < 8; ++nt) {
            uint32_t b[2];
            int jr = nt * 8 + gid;
            b[0] = kh32[jr * (QKS / 2) + ks * 8 + tg    ];
            b[1] = kh32[jr * (QKS / 2) + ks * 8 + tg + 4];
            mma_f16(sacc[nt], a, b);
        }
    }

    // ---- bias + mask + softmax (registers + tg-lane shuffles) ----
    int ib0 = (r0 < N) ? (r0 / WS) * 13 + (r0 % WS) : 0;
    int ib1 = (r1 < N) ? (r1 / WS) * 13 + (r1 % WS) : 0;
    int rg0 = (r0 < N) ? rgn_s[r0] : -2;
    int rg1 = (r1 < N) ? rgn_s[r1] : -2;

    float mx0 = -1e30f, mx1 = -1e30f;
    #pragma unroll
    for (int nt = 0; nt < 8; ++nt) {
        int j0 = nt * 8 + tg * 2, j1 = j0 + 1;
        int jo0 = joff_s[j0], jo1 = joff_s[j1];
        int rj0 = rgn_s[j0],  rj1 = rgn_s[j1];
        float v00 = (j0 < N) ? sacc[nt][0] + cpb_s[ib0 + jo0] + (rj0 == rg0 ? 0.f : -100.f) : -1e30f;
        float v01 = (j1 < N) ? sacc[nt][1] + cpb_s[ib0 + jo1] + (rj1 == rg0 ? 0.f : -100.f) : -1e30f;
        float v10 = (j0 < N) ? sacc[nt][2] + cpb_s[ib1 + jo0] + (rj0 == rg1 ? 0.f : -100.f) : -1e30f;
        float v11 = (j1 < N) ? sacc[nt][3] + cpb_s[ib1 + jo1] + (rj1 == rg1 ? 0.f : -100.f) : -1e30f;
        sacc[nt][0] = v00; sacc[nt][1] = v01; sacc[nt][2] = v10; sacc[nt][3] = v11;
        mx0 = fmaxf(mx0, fmaxf(v00, v01));
        mx1 = fmaxf(mx1, fmaxf(v10, v11));
    }
    mx0 = fmaxf(mx0, __shfl_xor_sync(0xffffffffu, mx0, 1));
    mx0 = fmaxf(mx0, __shfl_xor_sync(0xffffffffu, mx0, 2));
    mx1 = fmaxf(mx1, __shfl_xor_sync(0xffffffffu, mx1, 1));
    mx1 = fmaxf(mx1, __shfl_xor_sync(0xffffffffu, mx1, 2));

    float sm0 = 0.0f, sm1 = 0.0f;
    #pragma unroll
    for (int nt = 0; nt < 8; ++nt) {
        sacc[nt][0] = __expf(sacc[nt][0] - mx0);
        sacc[nt][1] = __expf(sacc[nt][1] - mx0);
        sacc[nt][2] = __expf(sacc[nt][2] - mx1);
        sacc[nt][3] = __expf(sacc[nt][3] - mx1);
        sm0 += sacc[nt][0] + sacc[nt][1];
        sm1 += sacc[nt][2] + sacc[nt][3];
    }
    sm0 += __shfl_xor_sync(0xffffffffu, sm0, 1);
    sm0 += __shfl_xor_sync(0xffffffffu, sm0, 2);
    sm1 += __shfl_xor_sync(0xffffffffu, sm1, 1);
    sm1 += __shfl_xor_sync(0xffffffffu, sm1, 2);
    float inv0 = 1.0f / sm0, inv1 = 1.0f / sm1;

    // pack P into A-fragment registers (rows r0/r1, cols as n-tiles)
    uint32_t ph0[8], ph1[8];
    #pragma unroll
    for (int nt = 0; nt < 8; ++nt) {
        ph0[nt] = pack_half2(sacc[nt][0] * inv0, sacc[nt][1] * inv0);
        ph1[nt] = pack_half2(sacc[nt][2] * inv1, sacc[nt][3] * inv1);
    }

    // ---- O = P @ V  (16 x 32 per warp) ----
    float oacc[4][4];
    #pragma unroll
    for (int nt = 0; nt < 4; ++nt)
        #pragma unroll
        for (int e = 0; e < 4; ++e) oacc[nt][e] = 0.0f;

    #pragma unroll
    for (int ks = 0; ks < 4; ++ks) {
        uint32_t a[4];
        a[0] = ph0[2 * ks];
        a[1] = ph1[2 * ks];
        a[2] = ph0[2 * ks + 1];
        a[3] = ph1[2 * ks + 1];
        #pragma unroll
        for (int nt = 0; nt < 4; ++nt) {
            uint32_t b[2];
            int dr = nt * 8 + gid;
            b[0] = vT32[dr * (VTS / 2) + ks * 8 + tg    ];
            b[1] = vT32[dr * (VTS / 2) + ks * 8 + tg + 4];
            mma_f16(oacc[nt], a, b);
        }
    }

    // store (rows < 49 only), float2 per n-tile
    float* dst = g_win + (size_t)bw * N * C + h * HD;
    #pragma unroll
    for (int nt = 0; nt < 4; ++nt) {
        int d0 = nt * 8 + tg * 2;
        if (r0 < N)
            *reinterpret_cast<float2*>(&dst[(size_t)r0 * C + d0]) =
                make_float2(oacc[nt][0], oacc[nt][1]);
        if (r1 < N)
            *reinterpret_cast<float2*>(&dst[(size_t)r1 * C + d0]) =
                make_float2(oacc[nt][2], oacc[nt][3]);
    }
}

// ---------------- block-wide sum over 192 threads ---------------------------
__device__ __forceinline__ float block_sum192(float v, float* red) {
    #pragma unroll
    for (int o = 16; o > 0; o >>= 1) v += __shfl_down_sync(0xffffffffu, v, o);
    int wid = threadIdx.x >> 5;
    if ((threadIdx.x & 31) == 0) red[wid] = v;
    __syncthreads();
    float s = red[0] + red[1] + red[2] + red[3] + red[4] + red[5];
    __syncthreads();
    return s;
}

// hidden[dst] = x[dst] + LN1(proj[t]), with window-reverse + un-shift scatter
__global__ __launch_bounds__(192)
void postattn_kernel(const float* __restrict__ x,
                     const float* __restrict__ g1, const float* __restrict__ b1) {
    __shared__ float red[6];
    int t = blockIdx.x, c = threadIdx.x;
    int bw = t / N, n = t % N;
    int b  = bw / NW, w_ = bw % NW;
    int wy = w_ / WG, wx = w_ % WG;
    int hh = wy * WS + n / WS, ww = wx * WS + n % WS;
    int oh = (hh + SS) % Hh, ow = (ww + SS) % Ww;
    size_t dst = ((size_t)(b * Hh + oh) * Ww + ow) * C;

    float v = g_q[(size_t)t * C + c];          // proj output row
    float mean = block_sum192(v, red) * (1.0f / C);
    float dv = v - mean;
    float var = block_sum192(dv * dv, red) * (1.0f / C);
    float ln = dv * rsqrtf(var + EPS) * g1[c] + b1[c];
    g_k[dst + c] = x[dst + c] + ln;            // hidden (natural layout)
}

// out[t] = hidden[t] + LN2(mlp[t])
__global__ __launch_bounds__(192)
void final_kernel(const float* __restrict__ g2, const float* __restrict__ b2,
                  float* __restrict__ out) {
    __shared__ float red[6];
    int t = blockIdx.x, c = threadIdx.x;
    float v = g_v[(size_t)t * C + c];          // mlp output row
    float mean = block_sum192(v, red) * (1.0f / C);
    float dv = v - mean;
    float var = block_sum192(dv * dv, red) * (1.0f / C);
    float ln = dv * rsqrtf(var + EPS) * g2[c] + b2[c];
    out[(size_t)t * C + c] = g_k[(size_t)t * C + c] + ln;
}

} // namespace

// ============================================================================
extern "C" void kernel_launch(void* const* d_in, const int* in_sizes, int n_in,
                              void* d_out, int out_size) {
    const float* x      = (const float*)d_in[0];
    const float* ln1_g  = (const float*)d_in[1];
    const float* ln1_b  = (const float*)d_in[2];
    const float* ln2_g  = (const float*)d_in[3];
    const float* ln2_b  = (const float*)d_in[4];
    const float* q_w    = (const float*)d_in[5];
    const float* q_b    = (const float*)d_in[6];
    const float* k_w    = (const float*)d_in[7];
    const float* v_w    = (const float*)d_in[8];
    const float* v_b    = (const float*)d_in[9];
    const float* p_w    = (const float*)d_in[10];
    const float* p_b    = (const float*)d_in[11];
    const float* lscale = (const float*)d_in[12];
    const float* cpb_w0 = (const float*)d_in[13];
    const float* cpb_b0 = (const float*)d_in[14];
    const float* cpb_w1 = (const float*)d_in[15];
    const float* fc1_w  = (const float*)d_in[16];
    const float* fc1_b  = (const float*)d_in[17];
    const float* fc2_w  = (const float*)d_in[18];
    const float* fc2_b  = (const float*)d_in[19];
    float* out = (float*)d_out;

    float *p_qkv, *p_win, *p_q, *p_k, *p_v, *p_m1, *p_bqkv;
    __half *p_wqkvT, *p_pwT, *p_fc1T, *p_fc2T;
    cudaGetSymbolAddress((void**)&p_qkv,   g_qkv);
    cudaGetSymbolAddress((void**)&p_win,   g_win);
    cudaGetSymbolAddress((void**)&p_q,     g_q);
    cudaGetSymbolAddress((void**)&p_k,     g_k);
    cudaGetSymbolAddress((void**)&p_v,     g_v);
    cudaGetSymbolAddress((void**)&p_m1,    g_mlp1);
    cudaGetSymbolAddress((void**)&p_bqkv,  g_bqkv);
    cudaGetSymbolAddress((void**)&p_wqkvT, g_wqkvT);
    cudaGetSymbolAddress((void**)&p_pwT,   g_pwT);
    cudaGetSymbolAddress((void**)&p_fc1T,  g_fc1T);
    cudaGetSymbolAddress((void**)&p_fc2T,  g_fc2T);

    // 1) CPB (16*sigmoid) table + head scales; pack/transpose weights to half
    cpb_kernel<<<169, 256>>>(cpb_w0, cpb_b0, cpb_w1, lscale);
    packqkvT_kernel<<<QKVC, 192>>>(q_w, k_w, v_w, q_b, v_b);
    packT_kernel<<<C,  192>>>(p_w,   p_pwT,  C,  C);
    packT_kernel<<<C4, 192>>>(fc1_w, p_fc1T, C,  C4);
    packT_kernel<<<C,  192>>>(fc2_w, p_fc2T, C4, C);

    // 2) fused shift+window-gather + QKV GEMM  (A = x with permuted rows)
    dim3 gQKV(QKVC / GBN, T / GBM);
    h16gemm_kernel<<<gQKV, 128>>>(x, p_wqkvT, p_bqkv, p_qkv, T, QKVC, C, 0, 1);

    // 3) fused attention (tensor-core; writes attn output into g_win)
    attn_kernel<<<BW * NH, 128>>>();

    // 4) output projection
    dim3 gC(C / GBN, T / GBM);
    h16gemm_kernel<<<gC, 128>>>(p_win, p_pwT, p_b, p_q, T, C, C, 0, 0);

    // 5) window reverse + un-shift + LN1 + residual -> hidden (g_k)
    postattn_kernel<<<T, C>>>(x, ln1_g, ln1_b);

    // 6) fc1 + GELU
    dim3 gF1(C4 / GBN, T / GBM);
    h16gemm_kernel<<<gF1, 128>>>(p_k, p_fc1T, fc1_b, p_m1, T, C4, C, 1, 0);

    // 7) fc2
    h16gemm_kernel<<<gC, 128>>>(p_m1, p_fc2T, fc2_b, p_v, T, C, C4, 0, 0);

    // 8) hidden + LN2(mlp) -> out
    final_kernel<<<T, C>>>(ln2_g, ln2_b, out);
}